// round 5
// baseline (speedup 1.0000x reference)
#include <cuda_runtime.h>
#include <math.h>
#include <stdint.h>

#define Bn     4
#define Cin    512
#define Tn     4
#define HW     961
#define THW    3844
#define CCn    256
#define CPn    42
#define CP3    126
#define AGGIN  1016
#define NLOC   61504
#define QT     64
#define JT     64

__device__ float d_xp [(size_t)Bn*Cin*THW];
__device__ float d_qmv[(size_t)Bn*768*THW];
__device__ float d_Qt [(size_t)Bn*THW*CCn];
__device__ float d_Vt [(size_t)Bn*THW*CCn];
__device__ float d_R  [(size_t)Bn*Tn*THW*CCn];
__device__ float d_Wt [256*168];
__device__ float d_Craw[(size_t)CP3*NLOC];
__device__ float d_Y  [(size_t)Bn*AGGIN*THW];
__device__ float d_Z  [(size_t)Bn*Cin*THW];
__device__ float d_cmean[CP3], d_crstd[CP3];
__device__ float d_zmean[Cin], d_zrstd[Cin];

__device__ __forceinline__ void sgemm_dev(const float* __restrict__ A,
                                          const float* __restrict__ Bp,
                                          float* __restrict__ Cp,
                                          int M, int N, int K,
                                          int lda, int ldb, int ldc, float alpha)
{
    __shared__ __align__(16) float As[8][128];
    __shared__ __align__(16) float Bs[8][128];
    const int tid = threadIdx.x;
    const int tx = tid & 15, ty = tid >> 4;
    const int m0 = blockIdx.y * 128, n0 = blockIdx.x * 128;
    float acc[8][8];
#pragma unroll
    for (int i = 0; i < 8; i++)
#pragma unroll
        for (int j = 0; j < 8; j++) acc[i][j] = 0.f;
    for (int k0 = 0; k0 < K; k0 += 8) {
#pragma unroll
        for (int i = 0; i < 4; i++) {
            int idx = tid + i * 256;
            int m = idx >> 3, k = idx & 7;
            int gm = m0 + m, gk = k0 + k;
            As[k][m] = (gm < M && gk < K) ? A[(size_t)gm * lda + gk] : 0.f;
        }
#pragma unroll
        for (int i = 0; i < 4; i++) {
            int idx = tid + i * 256;
            int k = idx >> 7, n = idx & 127;
            int gk = k0 + k, gn = n0 + n;
            Bs[k][n] = (gk < K && gn < N) ? Bp[(size_t)gk * ldb + gn] : 0.f;
        }
        __syncthreads();
#pragma unroll
        for (int k = 0; k < 8; k++) {
            float ra[8], rb[8];
            *(float4*)&ra[0] = *(const float4*)&As[k][ty * 8];
            *(float4*)&ra[4] = *(const float4*)&As[k][ty * 8 + 4];
            *(float4*)&rb[0] = *(const float4*)&Bs[k][tx * 8];
            *(float4*)&rb[4] = *(const float4*)&Bs[k][tx * 8 + 4];
#pragma unroll
            for (int i = 0; i < 8; i++)
#pragma unroll
                for (int j = 0; j < 8; j++)
                    acc[i][j] = fmaf(ra[i], rb[j], acc[i][j]);
        }
        __syncthreads();
    }
#pragma unroll
    for (int i = 0; i < 8; i++) {
        int gm = m0 + ty * 8 + i;
        if (gm >= M) continue;
#pragma unroll
        for (int j = 0; j < 8; j++) {
            int gn = n0 + tx * 8 + j;
            if (gn < N) Cp[(size_t)gm * ldc + gn] = acc[i][j] * alpha;
        }
    }
}

__global__ void __launch_bounds__(256) k_pool(const float* __restrict__ x)
{
    int idx = blockIdx.x * 256 + threadIdx.x;
    if (idx >= Bn * Cin * Tn * HW) return;
    int p = idx % HW; int rest = idx / HW;
    int h = p / 31, w = p % 31;
    const float* src = x + (size_t)rest * 3969 + (2 * h) * 63 + (2 * w);
    float v = src[0];
    v = fmaxf(v, src[1]);   v = fmaxf(v, src[2]);
    v = fmaxf(v, src[63]);  v = fmaxf(v, src[64]);  v = fmaxf(v, src[65]);
    v = fmaxf(v, src[126]); v = fmaxf(v, src[127]); v = fmaxf(v, src[128]);
    d_xp[idx] = v;
}

__global__ void __launch_bounds__(256) k_gemm_qmv(const float* __restrict__ Wq,
                                                  const float* __restrict__ Wm,
                                                  const float* __restrict__ Wv)
{
    int z = blockIdx.z; int b = z / 3, s = z % 3;
    const float* W = (s == 0) ? Wq : (s == 1) ? Wm : Wv;
    sgemm_dev(W, d_xp + (size_t)b * Cin * THW,
              d_qmv + (size_t)b * 768 * THW + (size_t)s * CCn * THW,
              CCn, THW, Cin, Cin, THW, THW, 1.f);
}

__global__ void __launch_bounds__(256) k_qvt()
{
    int idx = blockIdx.x * 256 + threadIdx.x;
    if (idx >= Bn * THW * CCn) return;
    int c = idx & 255; int r = idx >> 8;
    int q = r % THW; int b = r / THW;
    d_Qt[idx] = d_qmv[((size_t)b * 768 + c) * THW + q];
    d_Vt[idx] = d_qmv[((size_t)b * 768 + 512 + c) * THW + q];
}

// fused attention: R[(b,m)][q][c] = softmax_j(Q[q]·M[m,j]/16) @ V[m,j][c]
__global__ void __launch_bounds__(256) k_attn()
{
    const int b = blockIdx.z, m = blockIdx.y;
    const int q0 = blockIdx.x * QT;
    const int tid = threadIdx.x;
    const int tx = tid & 15, ty = tid >> 4;

    __shared__ __align__(16) float Qs[16][QT];
    __shared__ __align__(16) float Ms[16][JT];
    __shared__ __align__(16) float Ps[QT][JT + 4];
    __shared__ __align__(16) float Vs[16][CCn];

    const float* Qt = d_Qt + ((size_t)b * THW + q0) * CCn;
    const float* Mp = d_qmv + ((size_t)b * 768 + 256) * THW + m * HW;
    const float* Vt = d_Vt + ((size_t)b * THW + (size_t)m * HW) * CCn;

    float o[4][16], rmax[4], rsum[4];
#pragma unroll
    for (int i = 0; i < 4; i++) {
        rmax[i] = -1e30f; rsum[i] = 0.f;
#pragma unroll
        for (int j = 0; j < 16; j++) o[i][j] = 0.f;
    }

    for (int j0 = 0; j0 < HW; j0 += JT) {
        float s[4][4];
#pragma unroll
        for (int i = 0; i < 4; i++)
#pragma unroll
            for (int j = 0; j < 4; j++) s[i][j] = 0.f;
        for (int kc0 = 0; kc0 < CCn; kc0 += 16) {
#pragma unroll
            for (int u = 0; u < 4; u++) {
                int e = tid + u * 256;
                int kk = e >> 6, qq = e & 63;
                Qs[kk][qq] = (q0 + qq < THW) ? Qt[(size_t)qq * CCn + kc0 + kk] : 0.f;
            }
#pragma unroll
            for (int u = 0; u < 4; u++) {
                int e = tid + u * 256;
                int kk = e >> 6, jj = e & 63;
                Ms[kk][jj] = (j0 + jj < HW) ? Mp[(size_t)(kc0 + kk) * THW + j0 + jj] : 0.f;
            }
            __syncthreads();
#pragma unroll
            for (int kk = 0; kk < 16; kk++) {
                float a[4], bb[4];
#pragma unroll
                for (int i = 0; i < 4; i++) a[i] = Qs[kk][ty * 4 + i];
#pragma unroll
                for (int j = 0; j < 4; j++) bb[j] = Ms[kk][tx * 4 + j];
#pragma unroll
                for (int i = 0; i < 4; i++)
#pragma unroll
                    for (int j = 0; j < 4; j++)
                        s[i][j] = fmaf(a[i], bb[j], s[i][j]);
            }
            __syncthreads();
        }
#pragma unroll
        for (int i = 0; i < 4; i++) {
            float cmax = -1e30f;
#pragma unroll
            for (int j = 0; j < 4; j++) {
                s[i][j] *= (1.f / 16.f);
                if (j0 + tx * 4 + j < HW) cmax = fmaxf(cmax, s[i][j]);
            }
#pragma unroll
            for (int off = 1; off < 16; off <<= 1)
                cmax = fmaxf(cmax, __shfl_xor_sync(0xffffffffu, cmax, off));
            float nmax = fmaxf(rmax[i], cmax);
            float scale = expf(rmax[i] - nmax);
            float p[4], csum = 0.f;
#pragma unroll
            for (int j = 0; j < 4; j++) {
                p[j] = (j0 + tx * 4 + j < HW) ? expf(s[i][j] - nmax) : 0.f;
                csum += p[j];
            }
#pragma unroll
            for (int off = 1; off < 16; off <<= 1)
                csum += __shfl_xor_sync(0xffffffffu, csum, off);
            rsum[i] = rsum[i] * scale + csum;
            rmax[i] = nmax;
#pragma unroll
            for (int cj = 0; cj < 16; cj++) o[i][cj] *= scale;
#pragma unroll
            for (int j = 0; j < 4; j++) Ps[ty * 4 + i][tx * 4 + j] = p[j];
        }
        __syncthreads();
        for (int kj0 = 0; kj0 < JT; kj0 += 16) {
#pragma unroll
            for (int u = 0; u < 16; u++) {
                int e = tid + u * 256;
                int kj = e >> 8, c = e & 255;
                int gj = j0 + kj0 + kj;
                Vs[kj][c] = (gj < HW) ? Vt[(size_t)gj * CCn + c] : 0.f;
            }
            __syncthreads();
#pragma unroll
            for (int kj = 0; kj < 16; kj++) {
                float pv[4];
#pragma unroll
                for (int i = 0; i < 4; i++) pv[i] = Ps[ty * 4 + i][kj0 + kj];
                float vv[16];
                *(float4*)&vv[0]  = *(const float4*)&Vs[kj][tx * 16];
                *(float4*)&vv[4]  = *(const float4*)&Vs[kj][tx * 16 + 4];
                *(float4*)&vv[8]  = *(const float4*)&Vs[kj][tx * 16 + 8];
                *(float4*)&vv[12] = *(const float4*)&Vs[kj][tx * 16 + 12];
#pragma unroll
                for (int i = 0; i < 4; i++)
#pragma unroll
                    for (int cj = 0; cj < 16; cj++)
                        o[i][cj] = fmaf(pv[i], vv[cj], o[i][cj]);
            }
            __syncthreads();
        }
    }
    float* Rp = d_R + ((size_t)(b * 4 + m) * THW) * CCn;
#pragma unroll
    for (int i = 0; i < 4; i++) {
        int gq = q0 + ty * 4 + i;
        if (gq >= THW) continue;
        float inv = 1.f / rsum[i];
#pragma unroll
        for (int cj = 0; cj < 16; cj++)
            Rp[(size_t)gq * CCn + tx * 16 + cj] = o[i][cj] * inv;
    }
}

__global__ void __launch_bounds__(256) k_wtprep(const float* __restrict__ Wcat,
                                                const float* __restrict__ Wsub,
                                                const float* __restrict__ Wmul)
{
    int idx = blockIdx.x * 256 + threadIdx.x;
    if (idx >= 256 * 168) return;
    int wi = idx % 168, k = idx / 168;
    float v;
    if      (wi < 42)  v = Wcat[wi * 512 + k];
    else if (wi < 84)  v = Wcat[(wi - 42) * 512 + 256 + k];
    else if (wi < 126) v = Wsub[(wi - 84) * 256 + k];
    else               v = Wmul[(wi - 126) * 256 + k];
    d_Wt[idx] = v;
}

__global__ void __launch_bounds__(128) k_compare()
{
    __shared__ __align__(16) float Rs[256][16];
    __shared__ __align__(16) float Vsm[256][16];
    int loc0 = blockIdx.x * 16;
    int tid = threadIdx.x;
    for (int i = tid; i < 256 * 16; i += 128) {
        int c = i & 255, l = i >> 8;
        int loc = loc0 + l;
        int p = loc % HW; int bs = loc / HW;
        int s = bs & 15, b = bs >> 4;
        int tm = s >> 2, tq = s & 3;
        Rs[c][l]  = d_R [((size_t)((b * 4 + tm) * THW) + tq * HW + p) * CCn + c];
        Vsm[c][l] = d_Vt[((size_t)b * THW + tm * HW + p) * CCn + c];
    }
    __syncthreads();
    if (tid >= CP3) return;
    int o = tid;
    float acc[16];
#pragma unroll
    for (int l = 0; l < 16; l++) acc[l] = 0.f;
    if (o < CPn) {
        for (int k = 0; k < 256; k++) {
            float w1 = d_Wt[k * 168 + o];
            float w2 = d_Wt[k * 168 + 42 + o];
            const float4* rr = (const float4*)Rs[k];
            const float4* vv = (const float4*)Vsm[k];
#pragma unroll
            for (int q = 0; q < 4; q++) {
                float4 r = rr[q], v = vv[q];
                acc[q*4+0] = fmaf(w1, r.x, fmaf(w2, v.x, acc[q*4+0]));
                acc[q*4+1] = fmaf(w1, r.y, fmaf(w2, v.y, acc[q*4+1]));
                acc[q*4+2] = fmaf(w1, r.z, fmaf(w2, v.z, acc[q*4+2]));
                acc[q*4+3] = fmaf(w1, r.w, fmaf(w2, v.w, acc[q*4+3]));
            }
        }
    } else if (o < 2 * CPn) {
        for (int k = 0; k < 256; k++) {
            float w = d_Wt[k * 168 + 84 + (o - CPn)];
            const float4* rr = (const float4*)Rs[k];
            const float4* vv = (const float4*)Vsm[k];
#pragma unroll
            for (int q = 0; q < 4; q++) {
                float4 r = rr[q], v = vv[q];
                acc[q*4+0] = fmaf(w, r.x - v.x, acc[q*4+0]);
                acc[q*4+1] = fmaf(w, r.y - v.y, acc[q*4+1]);
                acc[q*4+2] = fmaf(w, r.z - v.z, acc[q*4+2]);
                acc[q*4+3] = fmaf(w, r.w - v.w, acc[q*4+3]);
            }
        }
    } else {
        for (int k = 0; k < 256; k++) {
            float w = d_Wt[k * 168 + 126 + (o - 2 * CPn)];
            const float4* rr = (const float4*)Rs[k];
            const float4* vv = (const float4*)Vsm[k];
#pragma unroll
            for (int q = 0; q < 4; q++) {
                float4 r = rr[q], v = vv[q];
                acc[q*4+0] = fmaf(w, r.x * v.x, acc[q*4+0]);
                acc[q*4+1] = fmaf(w, r.y * v.y, acc[q*4+1]);
                acc[q*4+2] = fmaf(w, r.z * v.z, acc[q*4+2]);
                acc[q*4+3] = fmaf(w, r.w * v.w, acc[q*4+3]);
            }
        }
    }
#pragma unroll
    for (int l = 0; l < 16; l++)
        d_Craw[(size_t)o * NLOC + loc0 + l] = acc[l];
}

// BN stats for compare branch: one block per channel (126). NO pointer args —
// device globals referenced directly (host-passed __device__ addresses go to the
// HOST shadow symbol under ATS: silent wrong answer; that was the round 1-4 bug).
__global__ void __launch_bounds__(256) k_stats_c()
{
    int ch = blockIdx.x;
    int tid = threadIdx.x;
    const float* p = d_Craw + (size_t)ch * NLOC;
    double s = 0.0, s2 = 0.0;
    for (int i = tid; i < NLOC; i += 256) {
        double v = (double)p[i];
        s += v; s2 += v * v;
    }
    __shared__ double sh[16];
#pragma unroll
    for (int off = 16; off; off >>= 1) {
        s  += __shfl_xor_sync(0xffffffffu, s,  off);
        s2 += __shfl_xor_sync(0xffffffffu, s2, off);
    }
    if ((tid & 31) == 0) { sh[tid >> 5] = s; sh[8 + (tid >> 5)] = s2; }
    __syncthreads();
    if (tid == 0) {
        double S = 0.0, S2 = 0.0;
        for (int i = 0; i < 8; i++) { S += sh[i]; S2 += sh[8 + i]; }
        double n = (double)NLOC;
        double mm = S / n;
        double var = S2 / n - mm * mm;
        d_cmean[ch] = (float)mm;
        d_crstd[ch] = (float)rsqrt(var + 1e-5);
    }
}

// BN stats for aggregate output: one block per channel (512), over 4 batches.
__global__ void __launch_bounds__(256) k_stats_z()
{
    int ch = blockIdx.x;
    int tid = threadIdx.x;
    double s = 0.0, s2 = 0.0;
    for (int b = 0; b < Bn; b++) {
        const float* p = d_Z + (size_t)b * Cin * THW + (size_t)ch * THW;
        for (int i = tid; i < THW; i += 256) {
            double v = (double)p[i];
            s += v; s2 += v * v;
        }
    }
    __shared__ double sh[16];
#pragma unroll
    for (int off = 16; off; off >>= 1) {
        s  += __shfl_xor_sync(0xffffffffu, s,  off);
        s2 += __shfl_xor_sync(0xffffffffu, s2, off);
    }
    if ((tid & 31) == 0) { sh[tid >> 5] = s; sh[8 + (tid >> 5)] = s2; }
    __syncthreads();
    if (tid == 0) {
        double S = 0.0, S2 = 0.0;
        for (int i = 0; i < 8; i++) { S += sh[i]; S2 += sh[8 + i]; }
        double n = (double)Bn * (double)THW;
        double mm = S / n;
        double var = S2 / n - mm * mm;
        d_zmean[ch] = (float)mm;
        d_zrstd[ch] = (float)rsqrt(var + 1e-5);
    }
}

__global__ void __launch_bounds__(256) k_ybuild(const float* __restrict__ gc, const float* __restrict__ bc,
                                                const float* __restrict__ gs, const float* __restrict__ bsv,
                                                const float* __restrict__ gm, const float* __restrict__ bmv)
{
    size_t idx = (size_t)blockIdx.x * 256 + threadIdx.x;
    if (idx >= (size_t)Bn * AGGIN * THW) return;
    int n = (int)(idx % THW);
    int rest = (int)(idx / THW);
    int ch = rest % AGGIN;
    int b = rest / AGGIN;
    int t = n / HW, p = n % HW;
    float val;
    if (ch < CCn) {
        size_t base = ((size_t)(b * 4 + t) * THW + p) * CCn + ch;
        val = 0.25f * (d_R[base] +
                       d_R[base + (size_t)1 * HW * CCn] +
                       d_R[base + (size_t)2 * HW * CCn] +
                       d_R[base + (size_t)3 * HW * CCn]);
    } else if (ch < 2 * CCn) {
        val = d_qmv[((size_t)b * 768 + 512 + (ch - CCn)) * THW + n];
    } else {
        int j = ch - 512;
        int c = j >> 2, tm = j & 3;
        size_t loc = (size_t)(b * 16 + tm * 4 + t) * HW + p;
        float raw = d_Craw[(size_t)c * NLOC + loc];
        float g, bb;
        if      (c < CPn)     { g = gc[c];           bb = bc[c]; }
        else if (c < 2 * CPn) { g = gs[c - CPn];     bb = bsv[c - CPn]; }
        else                  { g = gm[c - 2 * CPn]; bb = bmv[c - 2 * CPn]; }
        val = fmaxf((raw - d_cmean[c]) * d_crstd[c] * g + bb, 0.f);
    }
    d_Y[idx] = val;
}

__global__ void __launch_bounds__(256) k_gemm_agg(const float* __restrict__ Wagg)
{
    int b = blockIdx.z;
    sgemm_dev(Wagg, d_Y + (size_t)b * AGGIN * THW, d_Z + (size_t)b * Cin * THW,
              Cin, THW, AGGIN, AGGIN, THW, THW, 1.f);
}

__global__ void __launch_bounds__(256) k_finalize(const float* __restrict__ g,
                                                  const float* __restrict__ bv,
                                                  float* __restrict__ out)
{
    size_t idx = (size_t)blockIdx.x * 256 + threadIdx.x;
    if (idx >= (size_t)Bn * Cin * THW) return;
    int o = (int)((idx / THW) % Cin);
    float z = (d_Z[idx] - d_zmean[o]) * d_zrstd[o] * g[o] + bv[o];
    out[idx] = fmaxf(d_xp[idx] + z, 0.f);
}

extern "C" void kernel_launch(void* const* d_in, const int* in_sizes, int n_in,
                              void* d_out, int out_size)
{
    const float* x     = (const float*)d_in[0];
    const float* Wq    = (const float*)d_in[1];
    const float* Wm    = (const float*)d_in[2];
    const float* Wv    = (const float*)d_in[3];
    const float* Wcat  = (const float*)d_in[4];
    const float* Wsub  = (const float*)d_in[5];
    const float* Wmul  = (const float*)d_in[6];
    const float* g_cat = (const float*)d_in[7];
    const float* b_cat = (const float*)d_in[8];
    const float* g_sub = (const float*)d_in[9];
    const float* b_sub = (const float*)d_in[10];
    const float* g_mul = (const float*)d_in[11];
    const float* b_mul = (const float*)d_in[12];
    const float* Wagg  = (const float*)d_in[13];
    const float* g_agg = (const float*)d_in[14];
    const float* b_agg = (const float*)d_in[15];
    float* out = (float*)d_out;

    k_pool<<<(Bn * Cin * Tn * HW + 255) / 256, 256>>>(x);
    k_gemm_qmv<<<dim3((THW + 127) / 128, (CCn + 127) / 128, Bn * 3), 256>>>(Wq, Wm, Wv);
    k_qvt<<<(Bn * THW * CCn + 255) / 256, 256>>>();
    k_attn<<<dim3((THW + QT - 1) / QT, Tn, Bn), 256>>>();
    k_wtprep<<<(256 * 168 + 255) / 256, 256>>>(Wcat, Wsub, Wmul);
    k_compare<<<NLOC / 16, 128>>>();
    k_stats_c<<<CP3, 256>>>();
    k_ybuild<<<(int)(((size_t)Bn * AGGIN * THW + 255) / 256), 256>>>(g_cat, b_cat, g_sub, b_sub, g_mul, b_mul);
    k_gemm_agg<<<dim3((THW + 127) / 128, (Cin + 127) / 128, Bn), 256>>>(Wagg);
    k_stats_z<<<Cin, 256>>>();
    k_finalize<<<(Bn * Cin * THW + 255) / 256, 256>>>(g_agg, b_agg, out);
}

// round 6
// speedup vs baseline: 1.1186x; 1.1186x over previous
#include <cuda_runtime.h>
#include <math.h>
#include <stdint.h>

#define Bn     4
#define Cin    512
#define Tn     4
#define HW     961
#define THW    3844
#define CCn    256
#define CPn    42
#define CP3    126
#define AGGIN  1016
#define NLOC   61504
#define QT     64
#define JT     64
#define NQT    61           // ceil(3844/64)

typedef unsigned long long u64;

// ---------------- f32x2 packed-math helpers (sm_100+) ----------------
__device__ __forceinline__ u64 pack2(float lo, float hi) {
    u64 r; asm("mov.b64 %0, {%1,%2};" : "=l"(r) : "f"(lo), "f"(hi)); return r;
}
__device__ __forceinline__ u64 dup2(float v) { return pack2(v, v); }
__device__ __forceinline__ void unpack2(u64 p, float& lo, float& hi) {
    asm("mov.b64 {%0,%1}, %2;" : "=f"(lo), "=f"(hi) : "l"(p));
}
__device__ __forceinline__ u64 fma2(u64 a, u64 b, u64 c) {
    u64 d; asm("fma.rn.f32x2 %0, %1, %2, %3;" : "=l"(d) : "l"(a), "l"(b), "l"(c)); return d;
}
__device__ __forceinline__ u64 mul2(u64 a, u64 b) {
    u64 d; asm("mul.rn.f32x2 %0, %1, %2;" : "=l"(d) : "l"(a), "l"(b)); return d;
}

// ---------------- scratch ----------------
__device__ float d_xp [(size_t)Bn*Cin*THW];
__device__ float d_qmv[(size_t)Bn*768*THW];
__device__ float d_Qt [(size_t)Bn*THW*CCn];
__device__ float d_Vt [(size_t)Bn*THW*CCn];
__device__ float d_R  [(size_t)Bn*Tn*THW*CCn];
__device__ float d_Wt [256*168];
__device__ float d_Craw[(size_t)CP3*NLOC];
__device__ float d_Y  [(size_t)Bn*AGGIN*THW];
__device__ float d_Z  [(size_t)Bn*Cin*THW];
__device__ float d_cmean[CP3], d_crstd[CP3];
__device__ float d_zmean[Cin], d_zrstd[Cin];

// ---------------- double-buffered f32x2 SGEMM 128x128x8 ----------------
__device__ __forceinline__ void sg_load(const float* __restrict__ A,
                                        const float* __restrict__ Bp,
                                        float* __restrict__ Asb, float* __restrict__ Bsb,
                                        int M, int N, int K, int lda, int ldb,
                                        int m0, int n0, int k0, int tid)
{
#pragma unroll
    for (int i = 0; i < 4; i++) {
        int idx = tid + i * 256;
        int m = idx >> 3, k = idx & 7;
        int gm = m0 + m, gk = k0 + k;
        Asb[k * 128 + m] = (gm < M && gk < K) ? A[(size_t)gm * lda + gk] : 0.f;
    }
#pragma unroll
    for (int i = 0; i < 4; i++) {
        int idx = tid + i * 256;
        int k = idx >> 7, n = idx & 127;
        int gk = k0 + k, gn = n0 + n;
        Bsb[k * 128 + n] = (gk < K && gn < N) ? Bp[(size_t)gk * ldb + gn] : 0.f;
    }
}

__device__ __forceinline__ void sgemm_dev(const float* __restrict__ A,
                                          const float* __restrict__ Bp,
                                          float* __restrict__ Cp,
                                          int M, int N, int K,
                                          int lda, int ldb, int ldc, float alpha)
{
    __shared__ __align__(16) float As[2][8 * 128];
    __shared__ __align__(16) float Bs[2][8 * 128];
    const int tid = threadIdx.x;
    const int tx = tid & 15, ty = tid >> 4;
    const int m0 = blockIdx.y * 128, n0 = blockIdx.x * 128;

    u64 acc2[8][4];
#pragma unroll
    for (int i = 0; i < 8; i++)
#pragma unroll
        for (int j = 0; j < 4; j++) acc2[i][j] = 0ull;

    const int nt = (K + 7) / 8;
    sg_load(A, Bp, As[0], Bs[0], M, N, K, lda, ldb, m0, n0, 0, tid);
    __syncthreads();

    for (int t = 0; t < nt; t++) {
        if (t + 1 < nt)
            sg_load(A, Bp, As[(t + 1) & 1], Bs[(t + 1) & 1], M, N, K, lda, ldb,
                    m0, n0, (t + 1) * 8, tid);
        const float* Ab = As[t & 1];
        const float* Bb = Bs[t & 1];
#pragma unroll
        for (int k = 0; k < 8; k++) {
            float4 ra0 = *(const float4*)&Ab[k * 128 + ty * 8];
            float4 ra1 = *(const float4*)&Ab[k * 128 + ty * 8 + 4];
            ulonglong2 rb0 = *(const ulonglong2*)&Bb[k * 128 + tx * 8];
            ulonglong2 rb1 = *(const ulonglong2*)&Bb[k * 128 + tx * 8 + 4];
            u64 b2[4] = { rb0.x, rb0.y, rb1.x, rb1.y };
            float ra[8] = { ra0.x, ra0.y, ra0.z, ra0.w, ra1.x, ra1.y, ra1.z, ra1.w };
#pragma unroll
            for (int i = 0; i < 8; i++) {
                u64 a2 = dup2(ra[i]);
#pragma unroll
                for (int j = 0; j < 4; j++)
                    acc2[i][j] = fma2(a2, b2[j], acc2[i][j]);
            }
        }
        __syncthreads();
    }
#pragma unroll
    for (int i = 0; i < 8; i++) {
        int gm = m0 + ty * 8 + i;
        if (gm >= M) continue;
#pragma unroll
        for (int j = 0; j < 4; j++) {
            float c0, c1; unpack2(acc2[i][j], c0, c1);
            int gn = n0 + tx * 8 + j * 2;
            if (gn < N)     Cp[(size_t)gm * ldc + gn]     = c0 * alpha;
            if (gn + 1 < N) Cp[(size_t)gm * ldc + gn + 1] = c1 * alpha;
        }
    }
}

// ---------------- elementwise / prep kernels ----------------
__global__ void __launch_bounds__(256) k_pool(const float* __restrict__ x)
{
    int idx = blockIdx.x * 256 + threadIdx.x;
    if (idx >= Bn * Cin * Tn * HW) return;
    int p = idx % HW; int rest = idx / HW;
    int h = p / 31, w = p % 31;
    const float* src = x + (size_t)rest * 3969 + (2 * h) * 63 + (2 * w);
    float v = src[0];
    v = fmaxf(v, src[1]);   v = fmaxf(v, src[2]);
    v = fmaxf(v, src[63]);  v = fmaxf(v, src[64]);  v = fmaxf(v, src[65]);
    v = fmaxf(v, src[126]); v = fmaxf(v, src[127]); v = fmaxf(v, src[128]);
    d_xp[idx] = v;
}

__global__ void __launch_bounds__(256) k_gemm_qmv(const float* __restrict__ Wq,
                                                  const float* __restrict__ Wm,
                                                  const float* __restrict__ Wv)
{
    int z = blockIdx.z; int b = z / 3, s = z % 3;
    const float* W = (s == 0) ? Wq : (s == 1) ? Wm : Wv;
    sgemm_dev(W, d_xp + (size_t)b * Cin * THW,
              d_qmv + (size_t)b * 768 * THW + (size_t)s * CCn * THW,
              CCn, THW, Cin, Cin, THW, THW, 1.f);
}

__global__ void __launch_bounds__(256) k_qvt()
{
    int idx = blockIdx.x * 256 + threadIdx.x;
    if (idx >= Bn * THW * CCn) return;
    int c = idx & 255; int r = idx >> 8;
    int q = r % THW; int b = r / THW;
    d_Qt[idx] = d_qmv[((size_t)b * 768 + c) * THW + q];
    d_Vt[idx] = d_qmv[((size_t)b * 768 + 512 + c) * THW + q];
}

// ---------------- fused flash attention, f32x2 + resident Q + dbuf ----------------
// dynamic smem layout (floats):
//   Qsall [16][16][64]   offset 0      (16384)
//   Ms    [2][16][64]    offset 16384  (2048)
//   Ps    [64][68]       offset 18432  (4352)
//   Vs    [2][16][256]   offset 22784  (8192)
#define AT_QS 0
#define AT_MS 16384
#define AT_PS 18432
#define AT_VS 22784
#define AT_SMEM_BYTES ((30976) * 4)

__global__ void __launch_bounds__(256) k_attn()
{
    extern __shared__ __align__(16) float sm[];
    float* Qsall = sm + AT_QS;
    float* Msb   = sm + AT_MS;
    float* Psb   = sm + AT_PS;
    float* Vsb   = sm + AT_VS;

    const int b = blockIdx.z, m = blockIdx.y;
    const int q0 = blockIdx.x * QT;
    const int tid = threadIdx.x;
    const int tx = tid & 15, ty = tid >> 4;

    const float* Qt = d_Qt + ((size_t)b * THW + q0) * CCn;               // [q][c]
    const float* Mp = d_qmv + ((size_t)b * 768 + 256) * THW + m * HW;    // [c][j]
    const float* Vt = d_Vt + ((size_t)b * THW + (size_t)m * HW) * CCn;   // [j][c]

    // ---- load entire Q tile once: Qsall[s][kk][qq] = Qt[qq][s*16+kk] ----
#pragma unroll
    for (int u = 0; u < 16; u++) {
        int e = tid + u * 256;          // float4 index, 0..4095
        int qq = e >> 6, c4 = e & 63;
        int c = c4 * 4;
        float4 v = make_float4(0.f, 0.f, 0.f, 0.f);
        if (q0 + qq < THW) v = *(const float4*)&Qt[(size_t)qq * CCn + c];
        int s = c >> 4, kk = c & 15;
        Qsall[(s * 16 + kk + 0) * 64 + qq] = v.x;
        Qsall[(s * 16 + kk + 1) * 64 + qq] = v.y;
        Qsall[(s * 16 + kk + 2) * 64 + qq] = v.z;
        Qsall[(s * 16 + kk + 3) * 64 + qq] = v.w;
    }

    u64 o2[4][8];
    float rmax[4], rsum[4];
#pragma unroll
    for (int i = 0; i < 4; i++) {
        rmax[i] = -1e30f; rsum[i] = 0.f;
#pragma unroll
        for (int p = 0; p < 8; p++) o2[i][p] = 0ull;
    }

    for (int j0 = 0; j0 < HW; j0 += JT) {
        // ---- phase A: S = Qtile @ Mchunk, K=256 in 16 dbuf slices ----
        u64 s2[4][2];
#pragma unroll
        for (int i = 0; i < 4; i++) { s2[i][0] = 0ull; s2[i][1] = 0ull; }

        // prefetch M slice 0
#pragma unroll
        for (int u = 0; u < 4; u++) {
            int e = tid + u * 256;
            int kk = e >> 6, jj = e & 63;
            Msb[kk * 64 + jj] = (j0 + jj < HW) ? Mp[(size_t)kk * THW + j0 + jj] : 0.f;
        }
        __syncthreads();

        for (int s = 0; s < 16; s++) {
            if (s + 1 < 16) {
                int nb = (s + 1) & 1;
#pragma unroll
                for (int u = 0; u < 4; u++) {
                    int e = tid + u * 256;
                    int kk = e >> 6, jj = e & 63;
                    Msb[(nb * 16 + kk) * 64 + jj] =
                        (j0 + jj < HW) ? Mp[(size_t)((s + 1) * 16 + kk) * THW + j0 + jj] : 0.f;
                }
            }
            const float* Qs = Qsall + s * 16 * 64;
            const float* Ms = Msb + (s & 1) * 16 * 64;
#pragma unroll
            for (int kk = 0; kk < 16; kk++) {
                float4 af = *(const float4*)&Qs[kk * 64 + ty * 4];
                ulonglong2 bp = *(const ulonglong2*)&Ms[kk * 64 + tx * 4];
                u64 a0 = dup2(af.x), a1 = dup2(af.y), a2 = dup2(af.z), a3 = dup2(af.w);
                s2[0][0] = fma2(a0, bp.x, s2[0][0]); s2[0][1] = fma2(a0, bp.y, s2[0][1]);
                s2[1][0] = fma2(a1, bp.x, s2[1][0]); s2[1][1] = fma2(a1, bp.y, s2[1][1]);
                s2[2][0] = fma2(a2, bp.x, s2[2][0]); s2[2][1] = fma2(a2, bp.y, s2[2][1]);
                s2[3][0] = fma2(a3, bp.x, s2[3][0]); s2[3][1] = fma2(a3, bp.y, s2[3][1]);
            }
            __syncthreads();
        }

        // ---- phase B: online softmax ----
#pragma unroll
        for (int i = 0; i < 4; i++) {
            float sv[4];
            unpack2(s2[i][0], sv[0], sv[1]);
            unpack2(s2[i][1], sv[2], sv[3]);
            float cmax = -1e30f;
#pragma unroll
            for (int j = 0; j < 4; j++) {
                sv[j] *= (1.f / 16.f);
                if (j0 + tx * 4 + j < HW) cmax = fmaxf(cmax, sv[j]);
            }
#pragma unroll
            for (int off = 1; off < 16; off <<= 1)
                cmax = fmaxf(cmax, __shfl_xor_sync(0xffffffffu, cmax, off));
            float nmax = fmaxf(rmax[i], cmax);
            float scale = expf(rmax[i] - nmax);
            float p[4], csum = 0.f;
#pragma unroll
            for (int j = 0; j < 4; j++) {
                p[j] = (j0 + tx * 4 + j < HW) ? expf(sv[j] - nmax) : 0.f;
                csum += p[j];
            }
#pragma unroll
            for (int off = 1; off < 16; off <<= 1)
                csum += __shfl_xor_sync(0xffffffffu, csum, off);
            rsum[i] = rsum[i] * scale + csum;
            rmax[i] = nmax;
            u64 sc2 = dup2(scale);
#pragma unroll
            for (int pp = 0; pp < 8; pp++) o2[i][pp] = mul2(o2[i][pp], sc2);
            *(float4*)&Psb[(ty * 4 + i) * 68 + tx * 4] = make_float4(p[0], p[1], p[2], p[3]);
        }

        // ---- phase C: O += P @ Vchunk, 4 dbuf slices of 16 j ----
        // prefetch V slice 0
#pragma unroll
        for (int u = 0; u < 16; u++) {
            int e = tid + u * 256;
            int kj = e >> 8, c = e & 255;
            int gj = j0 + kj;
            Vsb[kj * 256 + c] = (gj < HW) ? Vt[(size_t)gj * CCn + c] : 0.f;
        }
        __syncthreads();   // covers Ps writes + Vs slice 0

        for (int sl = 0; sl < 4; sl++) {
            if (sl + 1 < 4) {
                int nb = (sl + 1) & 1;
#pragma unroll
                for (int u = 0; u < 16; u++) {
                    int e = tid + u * 256;
                    int kj = e >> 8, c = e & 255;
                    int gj = j0 + (sl + 1) * 16 + kj;
                    Vsb[(nb * 16 + kj) * 256 + c] = (gj < HW) ? Vt[(size_t)gj * CCn + c] : 0.f;
                }
            }
            const float* Vs = Vsb + (sl & 1) * 16 * 256;
#pragma unroll
            for (int kj = 0; kj < 16; kj++) {
                u64 pv2[4];
#pragma unroll
                for (int i = 0; i < 4; i++)
                    pv2[i] = dup2(Psb[(ty * 4 + i) * 68 + sl * 16 + kj]);
                ulonglong2 v0 = *(const ulonglong2*)&Vs[kj * 256 + tx * 16];
                ulonglong2 v1 = *(const ulonglong2*)&Vs[kj * 256 + tx * 16 + 4];
                ulonglong2 v2 = *(const ulonglong2*)&Vs[kj * 256 + tx * 16 + 8];
                ulonglong2 v3 = *(const ulonglong2*)&Vs[kj * 256 + tx * 16 + 12];
                u64 vp[8] = { v0.x, v0.y, v1.x, v1.y, v2.x, v2.y, v3.x, v3.y };
#pragma unroll
                for (int i = 0; i < 4; i++)
#pragma unroll
                    for (int pp = 0; pp < 8; pp++)
                        o2[i][pp] = fma2(pv2[i], vp[pp], o2[i][pp]);
            }
            __syncthreads();
        }
    }

    // ---- epilogue ----
    float* Rp = d_R + ((size_t)(b * 4 + m) * THW) * CCn;
#pragma unroll
    for (int i = 0; i < 4; i++) {
        int gq = q0 + ty * 4 + i;
        if (gq >= THW) continue;
        float inv = 1.f / rsum[i];
        float ob[16];
#pragma unroll
        for (int pp = 0; pp < 8; pp++) {
            float lo, hi; unpack2(o2[i][pp], lo, hi);
            ob[2 * pp] = lo * inv; ob[2 * pp + 1] = hi * inv;
        }
        float* dst = Rp + (size_t)gq * CCn + tx * 16;
        *(float4*)&dst[0]  = *(float4*)&ob[0];
        *(float4*)&dst[4]  = *(float4*)&ob[4];
        *(float4*)&dst[8]  = *(float4*)&ob[8];
        *(float4*)&dst[12] = *(float4*)&ob[12];
    }
}

__global__ void __launch_bounds__(256) k_wtprep(const float* __restrict__ Wcat,
                                                const float* __restrict__ Wsub,
                                                const float* __restrict__ Wmul)
{
    int idx = blockIdx.x * 256 + threadIdx.x;
    if (idx >= 256 * 168) return;
    int wi = idx % 168, k = idx / 168;
    float v;
    if      (wi < 42)  v = Wcat[wi * 512 + k];
    else if (wi < 84)  v = Wcat[(wi - 42) * 512 + 256 + k];
    else if (wi < 126) v = Wsub[(wi - 84) * 256 + k];
    else               v = Wmul[(wi - 126) * 256 + k];
    d_Wt[idx] = v;
}

__global__ void __launch_bounds__(128) k_compare()
{
    __shared__ __align__(16) float Rs[256][16];
    __shared__ __align__(16) float Vsm[256][16];
    int loc0 = blockIdx.x * 16;
    int tid = threadIdx.x;
    for (int i = tid; i < 256 * 16; i += 128) {
        int c = i & 255, l = i >> 8;
        int loc = loc0 + l;
        int p = loc % HW; int bs = loc / HW;
        int s = bs & 15, b = bs >> 4;
        int tm = s >> 2, tq = s & 3;
        Rs[c][l]  = d_R [((size_t)((b * 4 + tm) * THW) + tq * HW + p) * CCn + c];
        Vsm[c][l] = d_Vt[((size_t)b * THW + tm * HW + p) * CCn + c];
    }
    __syncthreads();
    if (tid >= CP3) return;
    int o = tid;
    u64 acc2[8];
#pragma unroll
    for (int p = 0; p < 8; p++) acc2[p] = 0ull;

    if (o < CPn) {
        for (int k = 0; k < 256; k++) {
            u64 w1d = dup2(d_Wt[k * 168 + o]);
            u64 w2d = dup2(d_Wt[k * 168 + 42 + o]);
            const u64* rr = (const u64*)Rs[k];
            const u64* vv = (const u64*)Vsm[k];
#pragma unroll
            for (int p = 0; p < 8; p++)
                acc2[p] = fma2(w1d, rr[p], fma2(w2d, vv[p], acc2[p]));
        }
    } else if (o < 2 * CPn) {
        for (int k = 0; k < 256; k++) {
            float w = d_Wt[k * 168 + 84 + (o - CPn)];
            u64 wd = dup2(w), wnd = dup2(-w);
            const u64* rr = (const u64*)Rs[k];
            const u64* vv = (const u64*)Vsm[k];
#pragma unroll
            for (int p = 0; p < 8; p++)
                acc2[p] = fma2(wd, rr[p], fma2(wnd, vv[p], acc2[p]));
        }
    } else {
        for (int k = 0; k < 256; k++) {
            u64 wd = dup2(d_Wt[k * 168 + 126 + (o - 2 * CPn)]);
            const u64* rr = (const u64*)Rs[k];
            const u64* vv = (const u64*)Vsm[k];
#pragma unroll
            for (int p = 0; p < 8; p++)
                acc2[p] = fma2(wd, mul2(rr[p], vv[p]), acc2[p]);
        }
    }
    float outv[16];
#pragma unroll
    for (int p = 0; p < 8; p++) unpack2(acc2[p], outv[2 * p], outv[2 * p + 1]);
#pragma unroll
    for (int l = 0; l < 16; l++)
        d_Craw[(size_t)o * NLOC + loc0 + l] = outv[l];
}

// BN stats — argument-free, device globals referenced directly (ATS pitfall fix).
__global__ void __launch_bounds__(256) k_stats_c()
{
    int ch = blockIdx.x;
    int tid = threadIdx.x;
    const float* p = d_Craw + (size_t)ch * NLOC;
    double s = 0.0, s2 = 0.0;
    for (int i = tid; i < NLOC; i += 256) {
        double v = (double)p[i];
        s += v; s2 += v * v;
    }
    __shared__ double sh[16];
#pragma unroll
    for (int off = 16; off; off >>= 1) {
        s  += __shfl_xor_sync(0xffffffffu, s,  off);
        s2 += __shfl_xor_sync(0xffffffffu, s2, off);
    }
    if ((tid & 31) == 0) { sh[tid >> 5] = s; sh[8 + (tid >> 5)] = s2; }
    __syncthreads();
    if (tid == 0) {
        double S = 0.0, S2 = 0.0;
        for (int i = 0; i < 8; i++) { S += sh[i]; S2 += sh[8 + i]; }
        double n = (double)NLOC;
        double mm = S / n;
        double var = S2 / n - mm * mm;
        d_cmean[ch] = (float)mm;
        d_crstd[ch] = (float)rsqrt(var + 1e-5);
    }
}

__global__ void __launch_bounds__(256) k_stats_z()
{
    int ch = blockIdx.x;
    int tid = threadIdx.x;
    double s = 0.0, s2 = 0.0;
    for (int b = 0; b < Bn; b++) {
        const float* p = d_Z + (size_t)b * Cin * THW + (size_t)ch * THW;
        for (int i = tid; i < THW; i += 256) {
            double v = (double)p[i];
            s += v; s2 += v * v;
        }
    }
    __shared__ double sh[16];
#pragma unroll
    for (int off = 16; off; off >>= 1) {
        s  += __shfl_xor_sync(0xffffffffu, s,  off);
        s2 += __shfl_xor_sync(0xffffffffu, s2, off);
    }
    if ((tid & 31) == 0) { sh[tid >> 5] = s; sh[8 + (tid >> 5)] = s2; }
    __syncthreads();
    if (tid == 0) {
        double S = 0.0, S2 = 0.0;
        for (int i = 0; i < 8; i++) { S += sh[i]; S2 += sh[8 + i]; }
        double n = (double)Bn * (double)THW;
        double mm = S / n;
        double var = S2 / n - mm * mm;
        d_zmean[ch] = (float)mm;
        d_zrstd[ch] = (float)rsqrt(var + 1e-5);
    }
}

__global__ void __launch_bounds__(256) k_ybuild(const float* __restrict__ gc, const float* __restrict__ bc,
                                                const float* __restrict__ gs, const float* __restrict__ bsv,
                                                const float* __restrict__ gm, const float* __restrict__ bmv)
{
    size_t idx = (size_t)blockIdx.x * 256 + threadIdx.x;
    if (idx >= (size_t)Bn * AGGIN * THW) return;
    int n = (int)(idx % THW);
    int rest = (int)(idx / THW);
    int ch = rest % AGGIN;
    int b = rest / AGGIN;
    int t = n / HW, p = n % HW;
    float val;
    if (ch < CCn) {
        size_t base = ((size_t)(b * 4 + t) * THW + p) * CCn + ch;
        val = 0.25f * (d_R[base] +
                       d_R[base + (size_t)1 * HW * CCn] +
                       d_R[base + (size_t)2 * HW * CCn] +
                       d_R[base + (size_t)3 * HW * CCn]);
    } else if (ch < 2 * CCn) {
        val = d_qmv[((size_t)b * 768 + 512 + (ch - CCn)) * THW + n];
    } else {
        int j = ch - 512;
        int c = j >> 2, tm = j & 3;
        size_t loc = (size_t)(b * 16 + tm * 4 + t) * HW + p;
        float raw = d_Craw[(size_t)c * NLOC + loc];
        float g, bb;
        if      (c < CPn)     { g = gc[c];           bb = bc[c]; }
        else if (c < 2 * CPn) { g = gs[c - CPn];     bb = bsv[c - CPn]; }
        else                  { g = gm[c - 2 * CPn]; bb = bmv[c - 2 * CPn]; }
        val = fmaxf((raw - d_cmean[c]) * d_crstd[c] * g + bb, 0.f);
    }
    d_Y[idx] = val;
}

__global__ void __launch_bounds__(256) k_gemm_agg(const float* __restrict__ Wagg)
{
    int b = blockIdx.z;
    sgemm_dev(Wagg, d_Y + (size_t)b * AGGIN * THW, d_Z + (size_t)b * Cin * THW,
              Cin, THW, AGGIN, AGGIN, THW, THW, 1.f);
}

__global__ void __launch_bounds__(256) k_finalize(const float* __restrict__ g,
                                                  const float* __restrict__ bv,
                                                  float* __restrict__ out)
{
    size_t idx = (size_t)blockIdx.x * 256 + threadIdx.x;
    if (idx >= (size_t)Bn * Cin * THW) return;
    int o = (int)((idx / THW) % Cin);
    float z = (d_Z[idx] - d_zmean[o]) * d_zrstd[o] * g[o] + bv[o];
    out[idx] = fmaxf(d_xp[idx] + z, 0.f);
}

extern "C" void kernel_launch(void* const* d_in, const int* in_sizes, int n_in,
                              void* d_out, int out_size)
{
    const float* x     = (const float*)d_in[0];
    const float* Wq    = (const float*)d_in[1];
    const float* Wm    = (const float*)d_in[2];
    const float* Wv    = (const float*)d_in[3];
    const float* Wcat  = (const float*)d_in[4];
    const float* Wsub  = (const float*)d_in[5];
    const float* Wmul  = (const float*)d_in[6];
    const float* g_cat = (const float*)d_in[7];
    const float* b_cat = (const float*)d_in[8];
    const float* g_sub = (const float*)d_in[9];
    const float* b_sub = (const float*)d_in[10];
    const float* g_mul = (const float*)d_in[11];
    const float* b_mul = (const float*)d_in[12];
    const float* Wagg  = (const float*)d_in[13];
    const float* g_agg = (const float*)d_in[14];
    const float* b_agg = (const float*)d_in[15];
    float* out = (float*)d_out;

    cudaFuncSetAttribute(k_attn, cudaFuncAttributeMaxDynamicSharedMemorySize, AT_SMEM_BYTES);

    k_pool<<<(Bn * Cin * Tn * HW + 255) / 256, 256>>>(x);
    k_gemm_qmv<<<dim3((THW + 127) / 128, (CCn + 127) / 128, Bn * 3), 256>>>(Wq, Wm, Wv);
    k_qvt<<<(Bn * THW * CCn + 255) / 256, 256>>>();
    k_attn<<<dim3(NQT, Tn, Bn), 256, AT_SMEM_BYTES>>>();
    k_wtprep<<<(256 * 168 + 255) / 256, 256>>>(Wcat, Wsub, Wmul);
    k_compare<<<NLOC / 16, 128>>>();
    k_stats_c<<<CP3, 256>>>();
    k_ybuild<<<(int)(((size_t)Bn * AGGIN * THW + 255) / 256), 256>>>(g_cat, b_cat, g_sub, b_sub, g_mul, b_mul);
    k_gemm_agg<<<dim3((THW + 127) / 128, (Cin + 127) / 128, Bn), 256>>>(Wagg);
    k_stats_z<<<Cin, 256>>>();
    k_finalize<<<(Bn * Cin * THW + 255) / 256, 256>>>(g_agg, b_agg, out);
}

// round 7
// speedup vs baseline: 2.3196x; 2.0736x over previous
#include <cuda_runtime.h>
#include <math.h>
#include <stdint.h>

#define Bn     4
#define Cin    512
#define Tn     4
#define HW     961
#define THW    3844
#define CCn    256
#define CPn    42
#define CP3    126
#define AGGIN  1016
#define NLOC   61504
#define NQT    61           // ceil(3844/64)

typedef unsigned long long u64;
typedef unsigned int u32;

// ---------------- f32x2 packed-math helpers ----------------
__device__ __forceinline__ u64 pack2(float lo, float hi) {
    u64 r; asm("mov.b64 %0, {%1,%2};" : "=l"(r) : "f"(lo), "f"(hi)); return r;
}
__device__ __forceinline__ u64 dup2(float v) { return pack2(v, v); }
__device__ __forceinline__ void unpack2(u64 p, float& lo, float& hi) {
    asm("mov.b64 {%0,%1}, %2;" : "=f"(lo), "=f"(hi) : "l"(p));
}
__device__ __forceinline__ u64 fma2(u64 a, u64 b, u64 c) {
    u64 d; asm("fma.rn.f32x2 %0, %1, %2, %3;" : "=l"(d) : "l"(a), "l"(b), "l"(c)); return d;
}
__device__ __forceinline__ u64 mul2(u64 a, u64 b) {
    u64 d; asm("mul.rn.f32x2 %0, %1, %2;" : "=l"(d) : "l"(a), "l"(b)); return d;
}

// ---------------- tf32 mma helpers ----------------
__device__ __forceinline__ u32 f2tf(float f) {
    u32 r; asm("cvt.rna.tf32.f32 %0, %1;" : "=r"(r) : "f"(f)); return r;
}
__device__ __forceinline__ void mma_tf32(float& d0, float& d1, float& d2, float& d3,
                                         u32 a0, u32 a1, u32 a2, u32 a3,
                                         u32 b0, u32 b1)
{
    asm("mma.sync.aligned.m16n8k8.row.col.f32.tf32.tf32.f32 "
        "{%0,%1,%2,%3},{%4,%5,%6,%7},{%8,%9},{%0,%1,%2,%3};"
        : "+f"(d0), "+f"(d1), "+f"(d2), "+f"(d3)
        : "r"(a0), "r"(a1), "r"(a2), "r"(a3), "r"(b0), "r"(b1));
}

// ---------------- scratch ----------------
__device__ float d_xp [(size_t)Bn*Cin*THW];
__device__ float d_qmv[(size_t)Bn*768*THW];
__device__ float d_Qt [(size_t)Bn*THW*CCn];          // [b][q][c]
__device__ float d_Mt [(size_t)Bn*THW*CCn];          // [b][j][c]
__device__ float d_Vt [(size_t)Bn*THW*CCn];          // [b][j][c]
__device__ float d_R  [(size_t)Bn*Tn*THW*CCn];
__device__ float d_Wt [256*168];
__device__ float d_Craw[(size_t)CP3*NLOC];
__device__ float d_Y  [(size_t)Bn*AGGIN*THW];
__device__ float d_Z  [(size_t)Bn*Cin*THW];
__device__ float d_cmean[CP3], d_crstd[CP3];
__device__ float d_zmean[Cin], d_zrstd[Cin];

// ---------------- double-buffered f32x2 SGEMM 128x128x8 ----------------
__device__ __forceinline__ void sg_load(const float* __restrict__ A,
                                        const float* __restrict__ Bp,
                                        float* __restrict__ Asb, float* __restrict__ Bsb,
                                        int M, int N, int K, int lda, int ldb,
                                        int m0, int n0, int k0, int tid)
{
#pragma unroll
    for (int i = 0; i < 4; i++) {
        int idx = tid + i * 256;
        int m = idx >> 3, k = idx & 7;
        int gm = m0 + m, gk = k0 + k;
        Asb[k * 128 + m] = (gm < M && gk < K) ? A[(size_t)gm * lda + gk] : 0.f;
    }
#pragma unroll
    for (int i = 0; i < 4; i++) {
        int idx = tid + i * 256;
        int k = idx >> 7, n = idx & 127;
        int gk = k0 + k, gn = n0 + n;
        Bsb[k * 128 + n] = (gk < K && gn < N) ? Bp[(size_t)gk * ldb + gn] : 0.f;
    }
}

__device__ __forceinline__ void sgemm_dev(const float* __restrict__ A,
                                          const float* __restrict__ Bp,
                                          float* __restrict__ Cp,
                                          int M, int N, int K,
                                          int lda, int ldb, int ldc, float alpha)
{
    __shared__ __align__(16) float As[2][8 * 128];
    __shared__ __align__(16) float Bs[2][8 * 128];
    const int tid = threadIdx.x;
    const int tx = tid & 15, ty = tid >> 4;
    const int m0 = blockIdx.y * 128, n0 = blockIdx.x * 128;

    u64 acc2[8][4];
#pragma unroll
    for (int i = 0; i < 8; i++)
#pragma unroll
        for (int j = 0; j < 4; j++) acc2[i][j] = 0ull;

    const int nt = (K + 7) / 8;
    sg_load(A, Bp, As[0], Bs[0], M, N, K, lda, ldb, m0, n0, 0, tid);
    __syncthreads();

    for (int t = 0; t < nt; t++) {
        if (t + 1 < nt)
            sg_load(A, Bp, As[(t + 1) & 1], Bs[(t + 1) & 1], M, N, K, lda, ldb,
                    m0, n0, (t + 1) * 8, tid);
        const float* Ab = As[t & 1];
        const float* Bb = Bs[t & 1];
#pragma unroll
        for (int k = 0; k < 8; k++) {
            float4 ra0 = *(const float4*)&Ab[k * 128 + ty * 8];
            float4 ra1 = *(const float4*)&Ab[k * 128 + ty * 8 + 4];
            ulonglong2 rb0 = *(const ulonglong2*)&Bb[k * 128 + tx * 8];
            ulonglong2 rb1 = *(const ulonglong2*)&Bb[k * 128 + tx * 8 + 4];
            u64 b2[4] = { rb0.x, rb0.y, rb1.x, rb1.y };
            float ra[8] = { ra0.x, ra0.y, ra0.z, ra0.w, ra1.x, ra1.y, ra1.z, ra1.w };
#pragma unroll
            for (int i = 0; i < 8; i++) {
                u64 a2 = dup2(ra[i]);
#pragma unroll
                for (int j = 0; j < 4; j++)
                    acc2[i][j] = fma2(a2, b2[j], acc2[i][j]);
            }
        }
        __syncthreads();
    }
#pragma unroll
    for (int i = 0; i < 8; i++) {
        int gm = m0 + ty * 8 + i;
        if (gm >= M) continue;
#pragma unroll
        for (int j = 0; j < 4; j++) {
            float c0, c1; unpack2(acc2[i][j], c0, c1);
            int gn = n0 + tx * 8 + j * 2;
            if (gn < N)     Cp[(size_t)gm * ldc + gn]     = c0 * alpha;
            if (gn + 1 < N) Cp[(size_t)gm * ldc + gn + 1] = c1 * alpha;
        }
    }
}

// ---------------- elementwise / prep ----------------
__global__ void __launch_bounds__(256) k_pool(const float* __restrict__ x)
{
    int idx = blockIdx.x * 256 + threadIdx.x;
    if (idx >= Bn * Cin * Tn * HW) return;
    int p = idx % HW; int rest = idx / HW;
    int h = p / 31, w = p % 31;
    const float* src = x + (size_t)rest * 3969 + (2 * h) * 63 + (2 * w);
    float v = src[0];
    v = fmaxf(v, src[1]);   v = fmaxf(v, src[2]);
    v = fmaxf(v, src[63]);  v = fmaxf(v, src[64]);  v = fmaxf(v, src[65]);
    v = fmaxf(v, src[126]); v = fmaxf(v, src[127]); v = fmaxf(v, src[128]);
    d_xp[idx] = v;
}

__global__ void __launch_bounds__(256) k_gemm_qmv(const float* __restrict__ Wq,
                                                  const float* __restrict__ Wm,
                                                  const float* __restrict__ Wv)
{
    int z = blockIdx.z; int b = z / 3, s = z % 3;
    const float* W = (s == 0) ? Wq : (s == 1) ? Wm : Wv;
    sgemm_dev(W, d_xp + (size_t)b * Cin * THW,
              d_qmv + (size_t)b * 768 * THW + (size_t)s * CCn * THW,
              CCn, THW, Cin, Cin, THW, THW, 1.f);
}

// tiled transpose: d_{Q,M,V}t[b][q][c] = qmv[b][s][c][q]
__global__ void __launch_bounds__(256) k_qvt()
{
    __shared__ float t[32][33];
    int z = blockIdx.z; int b = z / 3, s = z % 3;
    const float* src = d_qmv + ((size_t)b * 768 + s * 256) * THW;
    float* dst = (s == 0 ? d_Qt : (s == 1 ? d_Mt : d_Vt)) + (size_t)b * THW * CCn;
    int q0 = blockIdx.x * 32, c0 = blockIdx.y * 32;
    int tx = threadIdx.x & 31, ty = threadIdx.x >> 5;
#pragma unroll
    for (int i = 0; i < 4; i++) {
        int c = c0 + ty + i * 8;
        int q = q0 + tx;
        t[ty + i * 8][tx] = (q < THW) ? src[(size_t)c * THW + q] : 0.f;
    }
    __syncthreads();
#pragma unroll
    for (int i = 0; i < 4; i++) {
        int q = q0 + ty + i * 8;
        int c = c0 + tx;
        if (q < THW) dst[(size_t)q * CCn + c] = t[tx][ty + i * 8];
    }
}

// ---------------- tensor-core fused flash attention (tf32 mma) ----------------
// smem (u32/float units):
//   Qs  [64][260]  @0       16640   (tf32, q-tile resident)
//   Ms  [64][260]  @16640   16640   (tf32, M j-chunk)
//   Ps  [64][68]   @33280    4352   (tf32, probabilities)
//   Vs  [128][68]  @37632    8704   (tf32, V c-chunk x j)
//   SfM [2][64]    @46336     128   (f32 partial max)
//   SfS [2][64]    @46464     128   (f32 partial sum)
#define AT_SMEM_BYTES (46592 * 4)

__global__ void __launch_bounds__(256) k_attn()
{
    extern __shared__ __align__(16) u32 smu[];
    u32* Qs = smu;
    u32* Ms = smu + 16640;
    u32* Ps = smu + 33280;
    u32* Vs = smu + 37632;
    float* SfM = (float*)(smu + 46336);
    float* SfS = (float*)(smu + 46464);

    const int b = blockIdx.z, mfr = blockIdx.y;
    const int q0 = blockIdx.x * 64;
    const int tid = threadIdx.x;
    const int w = tid >> 5, lane = tid & 31;
    const int g = lane >> 2, q4 = lane & 3;
    const int qg = w & 3, jh = w >> 2;     // q-group (0..3), j-half / c-half (0..1)
    const int qb = qg * 16;

    const float* Qt = d_Qt + ((size_t)b * THW + q0) * CCn;
    const float* Mt = d_Mt + ((size_t)b * THW + (size_t)mfr * HW) * CCn;
    const float* Vg = d_qmv + ((size_t)b * 768 + 512) * THW + (size_t)mfr * HW; // [c][j]

    // load Q tile once (tf32)
#pragma unroll
    for (int p = 0; p < 16; p++) {
        int e4 = tid + p * 256;              // 0..4095
        int q = e4 >> 6, c = (e4 & 63) * 4;
        float4 v = make_float4(0.f, 0.f, 0.f, 0.f);
        if (q0 + q < THW) v = *(const float4*)&Qt[(size_t)q * CCn + c];
        u32* dst = &Qs[q * 260 + c];
        dst[0] = f2tf(v.x); dst[1] = f2tf(v.y); dst[2] = f2tf(v.z); dst[3] = f2tf(v.w);
    }

    float o[2][8][4];
#pragma unroll
    for (int v = 0; v < 2; v++)
#pragma unroll
        for (int n = 0; n < 8; n++)
#pragma unroll
            for (int i = 0; i < 4; i++) o[v][n][i] = 0.f;
    float rmax0 = -1e30f, rmax1 = -1e30f, rsum0 = 0.f, rsum1 = 0.f;

    for (int j0 = 0; j0 < HW; j0 += 64) {
        // ---- load M chunk (tf32) ----
#pragma unroll
        for (int p = 0; p < 16; p++) {
            int e4 = tid + p * 256;
            int j = e4 >> 6, c = (e4 & 63) * 4;
            float4 v = make_float4(0.f, 0.f, 0.f, 0.f);
            if (j0 + j < HW) v = *(const float4*)&Mt[(size_t)(j0 + j) * CCn + c];
            u32* dst = &Ms[j * 260 + c];
            dst[0] = f2tf(v.x); dst[1] = f2tf(v.y); dst[2] = f2tf(v.z); dst[3] = f2tf(v.w);
        }
        __syncthreads();

        // ---- phase A: S(16q x 32j per warp) = Q @ M^T via mma ----
        float s[4][4];
#pragma unroll
        for (int n = 0; n < 4; n++)
#pragma unroll
            for (int i = 0; i < 4; i++) s[n][i] = 0.f;
        const u32* Ar0 = &Qs[(qb + g) * 260];
        const u32* Ar1 = &Qs[(qb + g + 8) * 260];
#pragma unroll
        for (int ks = 0; ks < 32; ks++) {
            int kb = ks * 8 + q4;
            u32 a0 = Ar0[kb], a1 = Ar1[kb], a2 = Ar0[kb + 4], a3 = Ar1[kb + 4];
#pragma unroll
            for (int n = 0; n < 4; n++) {
                const u32* Br = &Ms[(jh * 32 + n * 8 + g) * 260];
                mma_tf32(s[n][0], s[n][1], s[n][2], s[n][3],
                         a0, a1, a2, a3, Br[kb], Br[kb + 4]);
            }
        }

        // ---- online softmax (cross-warp via smem) ----
        float mx0 = -1e30f, mx1 = -1e30f;
#pragma unroll
        for (int n = 0; n < 4; n++) {
            int cb = j0 + jh * 32 + n * 8 + q4 * 2;
            s[n][0] = (cb     < HW) ? s[n][0] * 0.0625f : -1e30f;
            s[n][1] = (cb + 1 < HW) ? s[n][1] * 0.0625f : -1e30f;
            s[n][2] = (cb     < HW) ? s[n][2] * 0.0625f : -1e30f;
            s[n][3] = (cb + 1 < HW) ? s[n][3] * 0.0625f : -1e30f;
            mx0 = fmaxf(mx0, fmaxf(s[n][0], s[n][1]));
            mx1 = fmaxf(mx1, fmaxf(s[n][2], s[n][3]));
        }
        mx0 = fmaxf(mx0, __shfl_xor_sync(0xffffffffu, mx0, 1));
        mx0 = fmaxf(mx0, __shfl_xor_sync(0xffffffffu, mx0, 2));
        mx1 = fmaxf(mx1, __shfl_xor_sync(0xffffffffu, mx1, 1));
        mx1 = fmaxf(mx1, __shfl_xor_sync(0xffffffffu, mx1, 2));
        if (q4 == 0) {
            SfM[jh * 64 + qb + g]     = mx0;
            SfM[jh * 64 + qb + g + 8] = mx1;
        }
        __syncthreads();
        float nm0 = fmaxf(rmax0, fmaxf(SfM[qb + g],     SfM[64 + qb + g]));
        float nm1 = fmaxf(rmax1, fmaxf(SfM[qb + g + 8], SfM[64 + qb + g + 8]));
        float es0 = expf(rmax0 - nm0), es1 = expf(rmax1 - nm1);
        rmax0 = nm0; rmax1 = nm1;
        float sm0 = 0.f, sm1 = 0.f;
#pragma unroll
        for (int n = 0; n < 4; n++) {
            int col = jh * 32 + n * 8 + q4 * 2;
            float p0 = expf(s[n][0] - nm0), p1 = expf(s[n][1] - nm0);
            float p2 = expf(s[n][2] - nm1), p3 = expf(s[n][3] - nm1);
            sm0 += p0 + p1; sm1 += p2 + p3;
            Ps[(qb + g) * 68 + col]         = f2tf(p0);
            Ps[(qb + g) * 68 + col + 1]     = f2tf(p1);
            Ps[(qb + g + 8) * 68 + col]     = f2tf(p2);
            Ps[(qb + g + 8) * 68 + col + 1] = f2tf(p3);
        }
        sm0 += __shfl_xor_sync(0xffffffffu, sm0, 1);
        sm0 += __shfl_xor_sync(0xffffffffu, sm0, 2);
        sm1 += __shfl_xor_sync(0xffffffffu, sm1, 1);
        sm1 += __shfl_xor_sync(0xffffffffu, sm1, 2);
        if (q4 == 0) {
            SfS[jh * 64 + qb + g]     = sm0;
            SfS[jh * 64 + qb + g + 8] = sm1;
        }
        __syncthreads();
        float cs0 = SfS[qb + g]     + SfS[64 + qb + g];
        float cs1 = SfS[qb + g + 8] + SfS[64 + qb + g + 8];
        rsum0 = rsum0 * es0 + cs0;
        rsum1 = rsum1 * es1 + cs1;
#pragma unroll
        for (int v = 0; v < 2; v++)
#pragma unroll
            for (int n = 0; n < 8; n++) {
                o[v][n][0] *= es0; o[v][n][1] *= es0;
                o[v][n][2] *= es1; o[v][n][3] *= es1;
            }

        // ---- phase C: O += P @ V (2 c-chunks of 128) ----
#pragma unroll
        for (int v = 0; v < 2; v++) {
#pragma unroll
            for (int p = 0; p < 32; p++) {
                int e = tid + p * 256;              // 0..8191
                int cr = e >> 6, j = e & 63;
                float val = 0.f;
                if (j0 + j < HW) val = Vg[(size_t)(v * 128 + cr) * THW + j0 + j];
                Vs[cr * 68 + j] = f2tf(val);
            }
            __syncthreads();
#pragma unroll
            for (int ks = 0; ks < 8; ks++) {
                int kb = ks * 8 + q4;
                u32 a0 = Ps[(qb + g) * 68 + kb];
                u32 a1 = Ps[(qb + g + 8) * 68 + kb];
                u32 a2 = Ps[(qb + g) * 68 + kb + 4];
                u32 a3 = Ps[(qb + g + 8) * 68 + kb + 4];
#pragma unroll
                for (int n = 0; n < 8; n++) {
                    const u32* Br = &Vs[(jh * 64 + n * 8 + g) * 68];
                    mma_tf32(o[v][n][0], o[v][n][1], o[v][n][2], o[v][n][3],
                             a0, a1, a2, a3, Br[kb], Br[kb + 4]);
                }
            }
            __syncthreads();
        }
    }

    // ---- epilogue: R = O / rsum ----
    float inv0 = 1.f / rsum0, inv1 = 1.f / rsum1;
    int r0 = q0 + qb + g, r1 = r0 + 8;
    float* Rp = d_R + ((size_t)(b * 4 + mfr) * THW) * CCn;
#pragma unroll
    for (int v = 0; v < 2; v++)
#pragma unroll
        for (int n = 0; n < 8; n++) {
            int c = v * 128 + jh * 64 + n * 8 + q4 * 2;
            if (r0 < THW) {
                float2 t0 = make_float2(o[v][n][0] * inv0, o[v][n][1] * inv0);
                *(float2*)&Rp[(size_t)r0 * CCn + c] = t0;
            }
            if (r1 < THW) {
                float2 t1 = make_float2(o[v][n][2] * inv1, o[v][n][3] * inv1);
                *(float2*)&Rp[(size_t)r1 * CCn + c] = t1;
            }
        }
}

__global__ void __launch_bounds__(256) k_wtprep(const float* __restrict__ Wcat,
                                                const float* __restrict__ Wsub,
                                                const float* __restrict__ Wmul)
{
    int idx = blockIdx.x * 256 + threadIdx.x;
    if (idx >= 256 * 168) return;
    int wi = idx % 168, k = idx / 168;
    float v;
    if      (wi < 42)  v = Wcat[wi * 512 + k];
    else if (wi < 84)  v = Wcat[(wi - 42) * 512 + 256 + k];
    else if (wi < 126) v = Wsub[(wi - 84) * 256 + k];
    else               v = Wmul[(wi - 126) * 256 + k];
    d_Wt[idx] = v;
}

__global__ void __launch_bounds__(128) k_compare()
{
    __shared__ __align__(16) float Rs[256][16];
    __shared__ __align__(16) float Vsm[256][16];
    int loc0 = blockIdx.x * 16;
    int tid = threadIdx.x;
    for (int i = tid; i < 256 * 16; i += 128) {
        int c = i & 255, l = i >> 8;
        int loc = loc0 + l;
        int p = loc % HW; int bs = loc / HW;
        int s = bs & 15, b = bs >> 4;
        int tm = s >> 2, tq = s & 3;
        Rs[c][l]  = d_R [((size_t)((b * 4 + tm) * THW) + tq * HW + p) * CCn + c];
        Vsm[c][l] = d_Vt[((size_t)b * THW + tm * HW + p) * CCn + c];
    }
    __syncthreads();
    if (tid >= CP3) return;
    int o = tid;
    u64 acc2[8];
#pragma unroll
    for (int p = 0; p < 8; p++) acc2[p] = 0ull;

    if (o < CPn) {
        for (int k = 0; k < 256; k++) {
            u64 w1d = dup2(d_Wt[k * 168 + o]);
            u64 w2d = dup2(d_Wt[k * 168 + 42 + o]);
            const u64* rr = (const u64*)Rs[k];
            const u64* vv = (const u64*)Vsm[k];
#pragma unroll
            for (int p = 0; p < 8; p++)
                acc2[p] = fma2(w1d, rr[p], fma2(w2d, vv[p], acc2[p]));
        }
    } else if (o < 2 * CPn) {
        for (int k = 0; k < 256; k++) {
            float w = d_Wt[k * 168 + 84 + (o - CPn)];
            u64 wd = dup2(w), wnd = dup2(-w);
            const u64* rr = (const u64*)Rs[k];
            const u64* vv = (const u64*)Vsm[k];
#pragma unroll
            for (int p = 0; p < 8; p++)
                acc2[p] = fma2(wd, rr[p], fma2(wnd, vv[p], acc2[p]));
        }
    } else {
        for (int k = 0; k < 256; k++) {
            u64 wd = dup2(d_Wt[k * 168 + 126 + (o - 2 * CPn)]);
            const u64* rr = (const u64*)Rs[k];
            const u64* vv = (const u64*)Vsm[k];
#pragma unroll
            for (int p = 0; p < 8; p++)
                acc2[p] = fma2(wd, mul2(rr[p], vv[p]), acc2[p]);
        }
    }
    float outv[16];
#pragma unroll
    for (int p = 0; p < 8; p++) unpack2(acc2[p], outv[2 * p], outv[2 * p + 1]);
#pragma unroll
    for (int l = 0; l < 16; l++)
        d_Craw[(size_t)o * NLOC + loc0 + l] = outv[l];
}

// BN stats — argument-free (GB300 ATS pitfall: host-passed __device__ addrs hit host shadow)
__global__ void __launch_bounds__(256) k_stats_c()
{
    int ch = blockIdx.x;
    int tid = threadIdx.x;
    const float* p = d_Craw + (size_t)ch * NLOC;
    double s = 0.0, s2 = 0.0;
    for (int i = tid; i < NLOC; i += 256) {
        double v = (double)p[i];
        s += v; s2 += v * v;
    }
    __shared__ double sh[16];
#pragma unroll
    for (int off = 16; off; off >>= 1) {
        s  += __shfl_xor_sync(0xffffffffu, s,  off);
        s2 += __shfl_xor_sync(0xffffffffu, s2, off);
    }
    if ((tid & 31) == 0) { sh[tid >> 5] = s; sh[8 + (tid >> 5)] = s2; }
    __syncthreads();
    if (tid == 0) {
        double S = 0.0, S2 = 0.0;
        for (int i = 0; i < 8; i++) { S += sh[i]; S2 += sh[8 + i]; }
        double n = (double)NLOC;
        double mm = S / n;
        double var = S2 / n - mm * mm;
        d_cmean[ch] = (float)mm;
        d_crstd[ch] = (float)rsqrt(var + 1e-5);
    }
}

__global__ void __launch_bounds__(256) k_stats_z()
{
    int ch = blockIdx.x;
    int tid = threadIdx.x;
    double s = 0.0, s2 = 0.0;
    for (int b = 0; b < Bn; b++) {
        const float* p = d_Z + (size_t)b * Cin * THW + (size_t)ch * THW;
        for (int i = tid; i < THW; i += 256) {
            double v = (double)p[i];
            s += v; s2 += v * v;
        }
    }
    __shared__ double sh[16];
#pragma unroll
    for (int off = 16; off; off >>= 1) {
        s  += __shfl_xor_sync(0xffffffffu, s,  off);
        s2 += __shfl_xor_sync(0xffffffffu, s2, off);
    }
    if ((tid & 31) == 0) { sh[tid >> 5] = s; sh[8 + (tid >> 5)] = s2; }
    __syncthreads();
    if (tid == 0) {
        double S = 0.0, S2 = 0.0;
        for (int i = 0; i < 8; i++) { S += sh[i]; S2 += sh[8 + i]; }
        double n = (double)Bn * (double)THW;
        double mm = S / n;
        double var = S2 / n - mm * mm;
        d_zmean[ch] = (float)mm;
        d_zrstd[ch] = (float)rsqrt(var + 1e-5);
    }
}

__global__ void __launch_bounds__(256) k_ybuild(const float* __restrict__ gc, const float* __restrict__ bc,
                                                const float* __restrict__ gs, const float* __restrict__ bsv,
                                                const float* __restrict__ gm, const float* __restrict__ bmv)
{
    size_t idx = (size_t)blockIdx.x * 256 + threadIdx.x;
    if (idx >= (size_t)Bn * AGGIN * THW) return;
    int n = (int)(idx % THW);
    int rest = (int)(idx / THW);
    int ch = rest % AGGIN;
    int b = rest / AGGIN;
    int t = n / HW, p = n % HW;
    float val;
    if (ch < CCn) {
        size_t base = ((size_t)(b * 4 + t) * THW + p) * CCn + ch;
        val = 0.25f * (d_R[base] +
                       d_R[base + (size_t)1 * HW * CCn] +
                       d_R[base + (size_t)2 * HW * CCn] +
                       d_R[base + (size_t)3 * HW * CCn]);
    } else if (ch < 2 * CCn) {
        val = d_qmv[((size_t)b * 768 + 512 + (ch - CCn)) * THW + n];
    } else {
        int j = ch - 512;
        int c = j >> 2, tm = j & 3;
        size_t loc = (size_t)(b * 16 + tm * 4 + t) * HW + p;
        float raw = d_Craw[(size_t)c * NLOC + loc];
        float g, bb;
        if      (c < CPn)     { g = gc[c];           bb = bc[c]; }
        else if (c < 2 * CPn) { g = gs[c - CPn];     bb = bsv[c - CPn]; }
        else                  { g = gm[c - 2 * CPn]; bb = bmv[c - 2 * CPn]; }
        val = fmaxf((raw - d_cmean[c]) * d_crstd[c] * g + bb, 0.f);
    }
    d_Y[idx] = val;
}

__global__ void __launch_bounds__(256) k_gemm_agg(const float* __restrict__ Wagg)
{
    int b = blockIdx.z;
    sgemm_dev(Wagg, d_Y + (size_t)b * AGGIN * THW, d_Z + (size_t)b * Cin * THW,
              Cin, THW, AGGIN, AGGIN, THW, THW, 1.f);
}

__global__ void __launch_bounds__(256) k_finalize(const float* __restrict__ g,
                                                  const float* __restrict__ bv,
                                                  float* __restrict__ out)
{
    size_t idx = (size_t)blockIdx.x * 256 + threadIdx.x;
    if (idx >= (size_t)Bn * Cin * THW) return;
    int o = (int)((idx / THW) % Cin);
    float z = (d_Z[idx] - d_zmean[o]) * d_zrstd[o] * g[o] + bv[o];
    out[idx] = fmaxf(d_xp[idx] + z, 0.f);
}

extern "C" void kernel_launch(void* const* d_in, const int* in_sizes, int n_in,
                              void* d_out, int out_size)
{
    const float* x     = (const float*)d_in[0];
    const float* Wq    = (const float*)d_in[1];
    const float* Wm    = (const float*)d_in[2];
    const float* Wv    = (const float*)d_in[3];
    const float* Wcat  = (const float*)d_in[4];
    const float* Wsub  = (const float*)d_in[5];
    const float* Wmul  = (const float*)d_in[6];
    const float* g_cat = (const float*)d_in[7];
    const float* b_cat = (const float*)d_in[8];
    const float* g_sub = (const float*)d_in[9];
    const float* b_sub = (const float*)d_in[10];
    const float* g_mul = (const float*)d_in[11];
    const float* b_mul = (const float*)d_in[12];
    const float* Wagg  = (const float*)d_in[13];
    const float* g_agg = (const float*)d_in[14];
    const float* b_agg = (const float*)d_in[15];
    float* out = (float*)d_out;

    cudaFuncSetAttribute(k_attn, cudaFuncAttributeMaxDynamicSharedMemorySize, AT_SMEM_BYTES);

    k_pool<<<(Bn * Cin * Tn * HW + 255) / 256, 256>>>(x);
    k_gemm_qmv<<<dim3((THW + 127) / 128, (CCn + 127) / 128, Bn * 3), 256>>>(Wq, Wm, Wv);
    k_qvt<<<dim3((THW + 31) / 32, CCn / 32, Bn * 3), 256>>>();
    k_attn<<<dim3(NQT, Tn, Bn), 256, AT_SMEM_BYTES>>>();
    k_wtprep<<<(256 * 168 + 255) / 256, 256>>>(Wcat, Wsub, Wmul);
    k_compare<<<NLOC / 16, 128>>>();
    k_stats_c<<<CP3, 256>>>();
    k_ybuild<<<(int)(((size_t)Bn * AGGIN * THW + 255) / 256), 256>>>(g_cat, b_cat, g_sub, b_sub, g_mul, b_mul);
    k_gemm_agg<<<dim3((THW + 127) / 128, (Cin + 127) / 128, Bn), 256>>>(Wagg);
    k_stats_z<<<Cin, 256>>>();
    k_finalize<<<(Bn * Cin * THW + 255) / 256, 256>>>(g_agg, b_agg, out);
}

// round 8
// speedup vs baseline: 2.5141x; 1.0839x over previous
#include <cuda_runtime.h>
#include <math.h>
#include <stdint.h>

#define Bn     4
#define Cin    512
#define Tn     4
#define HW     961
#define THW    3844
#define CCn    256
#define CPn    42
#define CP3    126
#define AGGIN  1016
#define NLOC   61504
#define NQT    61           // ceil(3844/64)
#define GP     17           // smem row pad (floats) for gemm3t

typedef unsigned long long u64;
typedef unsigned int u32;

// ---------------- f32x2 packed-math helpers ----------------
__device__ __forceinline__ u64 pack2(float lo, float hi) {
    u64 r; asm("mov.b64 %0, {%1,%2};" : "=l"(r) : "f"(lo), "f"(hi)); return r;
}
__device__ __forceinline__ u64 dup2(float v) { return pack2(v, v); }
__device__ __forceinline__ void unpack2(u64 p, float& lo, float& hi) {
    asm("mov.b64 {%0,%1}, %2;" : "=f"(lo), "=f"(hi) : "l"(p));
}
__device__ __forceinline__ u64 fma2(u64 a, u64 b, u64 c) {
    u64 d; asm("fma.rn.f32x2 %0, %1, %2, %3;" : "=l"(d) : "l"(a), "l"(b), "l"(c)); return d;
}
__device__ __forceinline__ u64 mul2(u64 a, u64 b) {
    u64 d; asm("mul.rn.f32x2 %0, %1, %2;" : "=l"(d) : "l"(a), "l"(b)); return d;
}

// ---------------- tf32 mma helpers ----------------
__device__ __forceinline__ u32 f2tf(float f) {
    u32 r; asm("cvt.rna.tf32.f32 %0, %1;" : "=r"(r) : "f"(f)); return r;
}
__device__ __forceinline__ void mma_tf32(float& d0, float& d1, float& d2, float& d3,
                                         u32 a0, u32 a1, u32 a2, u32 a3,
                                         u32 b0, u32 b1)
{
    asm("mma.sync.aligned.m16n8k8.row.col.f32.tf32.tf32.f32 "
        "{%0,%1,%2,%3},{%4,%5,%6,%7},{%8,%9},{%0,%1,%2,%3};"
        : "+f"(d0), "+f"(d1), "+f"(d2), "+f"(d3)
        : "r"(a0), "r"(a1), "r"(a2), "r"(a3), "r"(b0), "r"(b1));
}

// ---------------- scratch ----------------
__device__ float d_xp [(size_t)Bn*Cin*THW];
__device__ float d_qmv[(size_t)Bn*768*THW];
__device__ float d_Qt [(size_t)Bn*THW*CCn];          // [b][q][c]
__device__ float d_Mt [(size_t)Bn*THW*CCn];          // [b][j][c]
__device__ float d_Vt [(size_t)Bn*THW*CCn];          // [b][j][c]
__device__ float d_R  [(size_t)Bn*Tn*THW*CCn];
__device__ float d_Wt [256*168];
__device__ float d_Craw[(size_t)CP3*NLOC];
__device__ float d_Y  [(size_t)Bn*AGGIN*THW];
__device__ float d_Z  [(size_t)Bn*Cin*THW];
__device__ float d_cmean[CP3], d_crstd[CP3];
__device__ float d_zmean[Cin], d_zrstd[Cin];

// ---------------- 3xTF32 tensor-core GEMM, 128x128 block tile ----------------
// C(MxN) = alpha * A(MxK) @ B(KxN), row-major. M % 128 == 0 (grid exact), N even.
// 256 threads = 8 warps (4 M x 2 N), each warp 32x64 via m16n8k8.
__device__ __forceinline__ void gemm3t(const float* __restrict__ A,
                                       const float* __restrict__ B,
                                       float* __restrict__ C,
                                       int M, int N, int K,
                                       int lda, int ldb, int ldc, float alpha)
{
    __shared__ u32 Ah[128 * GP], Al[128 * GP];
    __shared__ u32 Bh[128 * GP], Bl[128 * GP];
    const int tid = threadIdx.x;
    const int lane = tid & 31, w = tid >> 5;
    const int g = lane >> 2, q4 = lane & 3;
    const int wm = w & 3, wn = w >> 2;               // 4 x 2 warp grid
    const int m0 = blockIdx.y * 128, n0 = blockIdx.x * 128;

    float acc[2][8][4];
#pragma unroll
    for (int mi = 0; mi < 2; mi++)
#pragma unroll
        for (int n = 0; n < 8; n++)
#pragma unroll
            for (int i = 0; i < 4; i++) acc[mi][n][i] = 0.f;

    const int nslice = (K + 15) / 16;
    for (int s = 0; s < nslice; s++) {
        const int k0 = s * 16;
        // ---- load A tile 128m x 16k, split hi/lo ----
#pragma unroll
        for (int i = 0; i < 2; i++) {
            int idx = tid + i * 256;                 // 0..511
            int row = idx >> 2, kc = (idx & 3) * 4;
            const float* src = A + (size_t)(m0 + row) * lda + k0 + kc;
#pragma unroll
            for (int j = 0; j < 4; j++) {
                float v = (k0 + kc + j < K) ? src[j] : 0.f;
                u32 h = f2tf(v);
                Ah[row * GP + kc + j] = h;
                Al[row * GP + kc + j] = f2tf(v - __uint_as_float(h));
            }
        }
        // ---- load B tile 16k x 128n -> smem [n][k], split hi/lo ----
#pragma unroll
        for (int i = 0; i < 2; i++) {
            int idx = tid + i * 256;
            int k = idx >> 5, n4 = (idx & 31) * 4;
            int gk = k0 + k;
            const float* src = B + (size_t)gk * ldb + n0 + n4;
            bool krow = (gk < K);
#pragma unroll
            for (int j = 0; j < 4; j++) {
                float v = (krow && n0 + n4 + j < N) ? src[j] : 0.f;
                u32 h = f2tf(v);
                Bh[(n4 + j) * GP + k] = h;
                Bl[(n4 + j) * GP + k] = f2tf(v - __uint_as_float(h));
            }
        }
        __syncthreads();

#pragma unroll
        for (int ks = 0; ks < 2; ks++) {
            int kb = ks * 8;
            u32 ah[2][4], al[2][4];
#pragma unroll
            for (int mi = 0; mi < 2; mi++) {
                int r0 = (wm * 32 + mi * 16 + g) * GP;
                int r1 = r0 + 8 * GP;
                ah[mi][0] = Ah[r0 + kb + q4];     ah[mi][1] = Ah[r1 + kb + q4];
                ah[mi][2] = Ah[r0 + kb + q4 + 4]; ah[mi][3] = Ah[r1 + kb + q4 + 4];
                al[mi][0] = Al[r0 + kb + q4];     al[mi][1] = Al[r1 + kb + q4];
                al[mi][2] = Al[r0 + kb + q4 + 4]; al[mi][3] = Al[r1 + kb + q4 + 4];
            }
#pragma unroll
            for (int n = 0; n < 8; n++) {
                int rb = (wn * 64 + n * 8 + g) * GP;
                u32 b0h = Bh[rb + kb + q4], b1h = Bh[rb + kb + q4 + 4];
                u32 b0l = Bl[rb + kb + q4], b1l = Bl[rb + kb + q4 + 4];
#pragma unroll
                for (int mi = 0; mi < 2; mi++) {
                    mma_tf32(acc[mi][n][0], acc[mi][n][1], acc[mi][n][2], acc[mi][n][3],
                             ah[mi][0], ah[mi][1], ah[mi][2], ah[mi][3], b0h, b1h);
                    mma_tf32(acc[mi][n][0], acc[mi][n][1], acc[mi][n][2], acc[mi][n][3],
                             ah[mi][0], ah[mi][1], ah[mi][2], ah[mi][3], b0l, b1l);
                    mma_tf32(acc[mi][n][0], acc[mi][n][1], acc[mi][n][2], acc[mi][n][3],
                             al[mi][0], al[mi][1], al[mi][2], al[mi][3], b0h, b1h);
                }
            }
        }
        __syncthreads();
    }

    // ---- epilogue (N even, so pair store safe when gn < N) ----
#pragma unroll
    for (int mi = 0; mi < 2; mi++) {
        int gm0 = m0 + wm * 32 + mi * 16 + g;
#pragma unroll
        for (int n = 0; n < 8; n++) {
            int gn = n0 + wn * 64 + n * 8 + q4 * 2;
            if (gn < N) {
                float2 t0 = make_float2(acc[mi][n][0] * alpha, acc[mi][n][1] * alpha);
                float2 t1 = make_float2(acc[mi][n][2] * alpha, acc[mi][n][3] * alpha);
                *(float2*)&C[(size_t)gm0 * ldc + gn] = t0;
                *(float2*)&C[(size_t)(gm0 + 8) * ldc + gn] = t1;
            }
        }
    }
}

// ---------------- elementwise / prep ----------------
__global__ void __launch_bounds__(256) k_pool(const float* __restrict__ x)
{
    int idx = blockIdx.x * 256 + threadIdx.x;
    if (idx >= Bn * Cin * Tn * HW) return;
    int p = idx % HW; int rest = idx / HW;
    int h = p / 31, w = p % 31;
    const float* src = x + (size_t)rest * 3969 + (2 * h) * 63 + (2 * w);
    float v = src[0];
    v = fmaxf(v, src[1]);   v = fmaxf(v, src[2]);
    v = fmaxf(v, src[63]);  v = fmaxf(v, src[64]);  v = fmaxf(v, src[65]);
    v = fmaxf(v, src[126]); v = fmaxf(v, src[127]); v = fmaxf(v, src[128]);
    d_xp[idx] = v;
}

__global__ void __launch_bounds__(256) k_gemm_qmv(const float* __restrict__ Wq,
                                                  const float* __restrict__ Wm,
                                                  const float* __restrict__ Wv)
{
    int z = blockIdx.z; int b = z / 3, s = z % 3;
    const float* W = (s == 0) ? Wq : (s == 1) ? Wm : Wv;
    gemm3t(W, d_xp + (size_t)b * Cin * THW,
           d_qmv + (size_t)b * 768 * THW + (size_t)s * CCn * THW,
           CCn, THW, Cin, Cin, THW, THW, 1.f);
}

// tiled transpose: d_{Q,M,V}t[b][q][c] = qmv[b][s][c][q]
__global__ void __launch_bounds__(256) k_qvt()
{
    __shared__ float t[32][33];
    int z = blockIdx.z; int b = z / 3, s = z % 3;
    const float* src = d_qmv + ((size_t)b * 768 + s * 256) * THW;
    float* dst = (s == 0 ? d_Qt : (s == 1 ? d_Mt : d_Vt)) + (size_t)b * THW * CCn;
    int q0 = blockIdx.x * 32, c0 = blockIdx.y * 32;
    int tx = threadIdx.x & 31, ty = threadIdx.x >> 5;
#pragma unroll
    for (int i = 0; i < 4; i++) {
        int c = c0 + ty + i * 8;
        int q = q0 + tx;
        t[ty + i * 8][tx] = (q < THW) ? src[(size_t)c * THW + q] : 0.f;
    }
    __syncthreads();
#pragma unroll
    for (int i = 0; i < 4; i++) {
        int q = q0 + ty + i * 8;
        int c = c0 + tx;
        if (q < THW) dst[(size_t)q * CCn + c] = t[tx][ty + i * 8];
    }
}

// ---------------- tensor-core fused flash attention (tf32 mma) ----------------
#define AT_SMEM_BYTES (46592 * 4)

__global__ void __launch_bounds__(256) k_attn()
{
    extern __shared__ __align__(16) u32 smu[];
    u32* Qs = smu;
    u32* Ms = smu + 16640;
    u32* Ps = smu + 33280;
    u32* Vs = smu + 37632;
    float* SfM = (float*)(smu + 46336);
    float* SfS = (float*)(smu + 46464);

    const int b = blockIdx.z, mfr = blockIdx.y;
    const int q0 = blockIdx.x * 64;
    const int tid = threadIdx.x;
    const int w = tid >> 5, lane = tid & 31;
    const int g = lane >> 2, q4 = lane & 3;
    const int qg = w & 3, jh = w >> 2;
    const int qb = qg * 16;

    const float* Qt = d_Qt + ((size_t)b * THW + q0) * CCn;
    const float* Mt = d_Mt + ((size_t)b * THW + (size_t)mfr * HW) * CCn;
    const float* Vg = d_qmv + ((size_t)b * 768 + 512) * THW + (size_t)mfr * HW;

#pragma unroll
    for (int p = 0; p < 16; p++) {
        int e4 = tid + p * 256;
        int q = e4 >> 6, c = (e4 & 63) * 4;
        float4 v = make_float4(0.f, 0.f, 0.f, 0.f);
        if (q0 + q < THW) v = *(const float4*)&Qt[(size_t)q * CCn + c];
        u32* dst = &Qs[q * 260 + c];
        dst[0] = f2tf(v.x); dst[1] = f2tf(v.y); dst[2] = f2tf(v.z); dst[3] = f2tf(v.w);
    }

    float o[2][8][4];
#pragma unroll
    for (int v = 0; v < 2; v++)
#pragma unroll
        for (int n = 0; n < 8; n++)
#pragma unroll
            for (int i = 0; i < 4; i++) o[v][n][i] = 0.f;
    float rmax0 = -1e30f, rmax1 = -1e30f, rsum0 = 0.f, rsum1 = 0.f;

    for (int j0 = 0; j0 < HW; j0 += 64) {
#pragma unroll
        for (int p = 0; p < 16; p++) {
            int e4 = tid + p * 256;
            int j = e4 >> 6, c = (e4 & 63) * 4;
            float4 v = make_float4(0.f, 0.f, 0.f, 0.f);
            if (j0 + j < HW) v = *(const float4*)&Mt[(size_t)(j0 + j) * CCn + c];
            u32* dst = &Ms[j * 260 + c];
            dst[0] = f2tf(v.x); dst[1] = f2tf(v.y); dst[2] = f2tf(v.z); dst[3] = f2tf(v.w);
        }
        __syncthreads();

        float s[4][4];
#pragma unroll
        for (int n = 0; n < 4; n++)
#pragma unroll
            for (int i = 0; i < 4; i++) s[n][i] = 0.f;
        const u32* Ar0 = &Qs[(qb + g) * 260];
        const u32* Ar1 = &Qs[(qb + g + 8) * 260];
#pragma unroll
        for (int ks = 0; ks < 32; ks++) {
            int kb = ks * 8 + q4;
            u32 a0 = Ar0[kb], a1 = Ar1[kb], a2 = Ar0[kb + 4], a3 = Ar1[kb + 4];
#pragma unroll
            for (int n = 0; n < 4; n++) {
                const u32* Br = &Ms[(jh * 32 + n * 8 + g) * 260];
                mma_tf32(s[n][0], s[n][1], s[n][2], s[n][3],
                         a0, a1, a2, a3, Br[kb], Br[kb + 4]);
            }
        }

        float mx0 = -1e30f, mx1 = -1e30f;
#pragma unroll
        for (int n = 0; n < 4; n++) {
            int cb = j0 + jh * 32 + n * 8 + q4 * 2;
            s[n][0] = (cb     < HW) ? s[n][0] * 0.0625f : -1e30f;
            s[n][1] = (cb + 1 < HW) ? s[n][1] * 0.0625f : -1e30f;
            s[n][2] = (cb     < HW) ? s[n][2] * 0.0625f : -1e30f;
            s[n][3] = (cb + 1 < HW) ? s[n][3] * 0.0625f : -1e30f;
            mx0 = fmaxf(mx0, fmaxf(s[n][0], s[n][1]));
            mx1 = fmaxf(mx1, fmaxf(s[n][2], s[n][3]));
        }
        mx0 = fmaxf(mx0, __shfl_xor_sync(0xffffffffu, mx0, 1));
        mx0 = fmaxf(mx0, __shfl_xor_sync(0xffffffffu, mx0, 2));
        mx1 = fmaxf(mx1, __shfl_xor_sync(0xffffffffu, mx1, 1));
        mx1 = fmaxf(mx1, __shfl_xor_sync(0xffffffffu, mx1, 2));
        if (q4 == 0) {
            SfM[jh * 64 + qb + g]     = mx0;
            SfM[jh * 64 + qb + g + 8] = mx1;
        }
        __syncthreads();
        float nm0 = fmaxf(rmax0, fmaxf(SfM[qb + g],     SfM[64 + qb + g]));
        float nm1 = fmaxf(rmax1, fmaxf(SfM[qb + g + 8], SfM[64 + qb + g + 8]));
        float es0 = expf(rmax0 - nm0), es1 = expf(rmax1 - nm1);
        rmax0 = nm0; rmax1 = nm1;
        float sm0 = 0.f, sm1 = 0.f;
#pragma unroll
        for (int n = 0; n < 4; n++) {
            int col = jh * 32 + n * 8 + q4 * 2;
            float p0 = expf(s[n][0] - nm0), p1 = expf(s[n][1] - nm0);
            float p2 = expf(s[n][2] - nm1), p3 = expf(s[n][3] - nm1);
            sm0 += p0 + p1; sm1 += p2 + p3;
            Ps[(qb + g) * 68 + col]         = f2tf(p0);
            Ps[(qb + g) * 68 + col + 1]     = f2tf(p1);
            Ps[(qb + g + 8) * 68 + col]     = f2tf(p2);
            Ps[(qb + g + 8) * 68 + col + 1] = f2tf(p3);
        }
        sm0 += __shfl_xor_sync(0xffffffffu, sm0, 1);
        sm0 += __shfl_xor_sync(0xffffffffu, sm0, 2);
        sm1 += __shfl_xor_sync(0xffffffffu, sm1, 1);
        sm1 += __shfl_xor_sync(0xffffffffu, sm1, 2);
        if (q4 == 0) {
            SfS[jh * 64 + qb + g]     = sm0;
            SfS[jh * 64 + qb + g + 8] = sm1;
        }
        __syncthreads();
        float cs0 = SfS[qb + g]     + SfS[64 + qb + g];
        float cs1 = SfS[qb + g + 8] + SfS[64 + qb + g + 8];
        rsum0 = rsum0 * es0 + cs0;
        rsum1 = rsum1 * es1 + cs1;
#pragma unroll
        for (int v = 0; v < 2; v++)
#pragma unroll
            for (int n = 0; n < 8; n++) {
                o[v][n][0] *= es0; o[v][n][1] *= es0;
                o[v][n][2] *= es1; o[v][n][3] *= es1;
            }

#pragma unroll
        for (int v = 0; v < 2; v++) {
#pragma unroll
            for (int p = 0; p < 32; p++) {
                int e = tid + p * 256;
                int cr = e >> 6, j = e & 63;
                float val = 0.f;
                if (j0 + j < HW) val = Vg[(size_t)(v * 128 + cr) * THW + j0 + j];
                Vs[cr * 68 + j] = f2tf(val);
            }
            __syncthreads();
#pragma unroll
            for (int ks = 0; ks < 8; ks++) {
                int kb = ks * 8 + q4;
                u32 a0 = Ps[(qb + g) * 68 + kb];
                u32 a1 = Ps[(qb + g + 8) * 68 + kb];
                u32 a2 = Ps[(qb + g) * 68 + kb + 4];
                u32 a3 = Ps[(qb + g + 8) * 68 + kb + 4];
#pragma unroll
                for (int n = 0; n < 8; n++) {
                    const u32* Br = &Vs[(jh * 64 + n * 8 + g) * 68];
                    mma_tf32(o[v][n][0], o[v][n][1], o[v][n][2], o[v][n][3],
                             a0, a1, a2, a3, Br[kb], Br[kb + 4]);
                }
            }
            __syncthreads();
        }
    }

    float inv0 = 1.f / rsum0, inv1 = 1.f / rsum1;
    int r0 = q0 + qb + g, r1 = r0 + 8;
    float* Rp = d_R + ((size_t)(b * 4 + mfr) * THW) * CCn;
#pragma unroll
    for (int v = 0; v < 2; v++)
#pragma unroll
        for (int n = 0; n < 8; n++) {
            int c = v * 128 + jh * 64 + n * 8 + q4 * 2;
            if (r0 < THW) {
                float2 t0 = make_float2(o[v][n][0] * inv0, o[v][n][1] * inv0);
                *(float2*)&Rp[(size_t)r0 * CCn + c] = t0;
            }
            if (r1 < THW) {
                float2 t1 = make_float2(o[v][n][2] * inv1, o[v][n][3] * inv1);
                *(float2*)&Rp[(size_t)r1 * CCn + c] = t1;
            }
        }
}

__global__ void __launch_bounds__(256) k_wtprep(const float* __restrict__ Wcat,
                                                const float* __restrict__ Wsub,
                                                const float* __restrict__ Wmul)
{
    int idx = blockIdx.x * 256 + threadIdx.x;
    if (idx >= 256 * 168) return;
    int wi = idx % 168, k = idx / 168;
    float v;
    if      (wi < 42)  v = Wcat[wi * 512 + k];
    else if (wi < 84)  v = Wcat[(wi - 42) * 512 + 256 + k];
    else if (wi < 126) v = Wsub[(wi - 84) * 256 + k];
    else               v = Wmul[(wi - 126) * 256 + k];
    d_Wt[idx] = v;
}

__global__ void __launch_bounds__(128) k_compare()
{
    __shared__ __align__(16) float Rs[256][16];
    __shared__ __align__(16) float Vsm[256][16];
    int loc0 = blockIdx.x * 16;
    int tid = threadIdx.x;
    for (int i = tid; i < 256 * 16; i += 128) {
        int c = i & 255, l = i >> 8;
        int loc = loc0 + l;
        int p = loc % HW; int bs = loc / HW;
        int s = bs & 15, b = bs >> 4;
        int tm = s >> 2, tq = s & 3;
        Rs[c][l]  = d_R [((size_t)((b * 4 + tm) * THW) + tq * HW + p) * CCn + c];
        Vsm[c][l] = d_Vt[((size_t)b * THW + tm * HW + p) * CCn + c];
    }
    __syncthreads();
    if (tid >= CP3) return;
    int o = tid;
    u64 acc2[8];
#pragma unroll
    for (int p = 0; p < 8; p++) acc2[p] = 0ull;

    if (o < CPn) {
        for (int k = 0; k < 256; k++) {
            u64 w1d = dup2(d_Wt[k * 168 + o]);
            u64 w2d = dup2(d_Wt[k * 168 + 42 + o]);
            const u64* rr = (const u64*)Rs[k];
            const u64* vv = (const u64*)Vsm[k];
#pragma unroll
            for (int p = 0; p < 8; p++)
                acc2[p] = fma2(w1d, rr[p], fma2(w2d, vv[p], acc2[p]));
        }
    } else if (o < 2 * CPn) {
        for (int k = 0; k < 256; k++) {
            float w = d_Wt[k * 168 + 84 + (o - CPn)];
            u64 wd = dup2(w), wnd = dup2(-w);
            const u64* rr = (const u64*)Rs[k];
            const u64* vv = (const u64*)Vsm[k];
#pragma unroll
            for (int p = 0; p < 8; p++)
                acc2[p] = fma2(wd, rr[p], fma2(wnd, vv[p], acc2[p]));
        }
    } else {
        for (int k = 0; k < 256; k++) {
            u64 wd = dup2(d_Wt[k * 168 + 126 + (o - 2 * CPn)]);
            const u64* rr = (const u64*)Rs[k];
            const u64* vv = (const u64*)Vsm[k];
#pragma unroll
            for (int p = 0; p < 8; p++)
                acc2[p] = fma2(wd, mul2(rr[p], vv[p]), acc2[p]);
        }
    }
    float outv[16];
#pragma unroll
    for (int p = 0; p < 8; p++) unpack2(acc2[p], outv[2 * p], outv[2 * p + 1]);
#pragma unroll
    for (int l = 0; l < 16; l++)
        d_Craw[(size_t)o * NLOC + loc0 + l] = outv[l];
}

// BN stats — argument-free (GB300 ATS pitfall: host-passed __device__ addrs hit host shadow)
__global__ void __launch_bounds__(256) k_stats_c()
{
    int ch = blockIdx.x;
    int tid = threadIdx.x;
    const float* p = d_Craw + (size_t)ch * NLOC;
    double s = 0.0, s2 = 0.0;
    for (int i = tid; i < NLOC; i += 256) {
        double v = (double)p[i];
        s += v; s2 += v * v;
    }
    __shared__ double sh[16];
#pragma unroll
    for (int off = 16; off; off >>= 1) {
        s  += __shfl_xor_sync(0xffffffffu, s,  off);
        s2 += __shfl_xor_sync(0xffffffffu, s2, off);
    }
    if ((tid & 31) == 0) { sh[tid >> 5] = s; sh[8 + (tid >> 5)] = s2; }
    __syncthreads();
    if (tid == 0) {
        double S = 0.0, S2 = 0.0;
        for (int i = 0; i < 8; i++) { S += sh[i]; S2 += sh[8 + i]; }
        double n = (double)NLOC;
        double mm = S / n;
        double var = S2 / n - mm * mm;
        d_cmean[ch] = (float)mm;
        d_crstd[ch] = (float)rsqrt(var + 1e-5);
    }
}

__global__ void __launch_bounds__(256) k_stats_z()
{
    int ch = blockIdx.x;
    int tid = threadIdx.x;
    double s = 0.0, s2 = 0.0;
    for (int b = 0; b < Bn; b++) {
        const float* p = d_Z + (size_t)b * Cin * THW + (size_t)ch * THW;
        for (int i = tid; i < THW; i += 256) {
            double v = (double)p[i];
            s += v; s2 += v * v;
        }
    }
    __shared__ double sh[16];
#pragma unroll
    for (int off = 16; off; off >>= 1) {
        s  += __shfl_xor_sync(0xffffffffu, s,  off);
        s2 += __shfl_xor_sync(0xffffffffu, s2, off);
    }
    if ((tid & 31) == 0) { sh[tid >> 5] = s; sh[8 + (tid >> 5)] = s2; }
    __syncthreads();
    if (tid == 0) {
        double S = 0.0, S2 = 0.0;
        for (int i = 0; i < 8; i++) { S += sh[i]; S2 += sh[8 + i]; }
        double n = (double)Bn * (double)THW;
        double mm = S / n;
        double var = S2 / n - mm * mm;
        d_zmean[ch] = (float)mm;
        d_zrstd[ch] = (float)rsqrt(var + 1e-5);
    }
}

__global__ void __launch_bounds__(256) k_ybuild(const float* __restrict__ gc, const float* __restrict__ bc,
                                                const float* __restrict__ gs, const float* __restrict__ bsv,
                                                const float* __restrict__ gm, const float* __restrict__ bmv)
{
    size_t idx = (size_t)blockIdx.x * 256 + threadIdx.x;
    if (idx >= (size_t)Bn * AGGIN * THW) return;
    int n = (int)(idx % THW);
    int rest = (int)(idx / THW);
    int ch = rest % AGGIN;
    int b = rest / AGGIN;
    int t = n / HW, p = n % HW;
    float val;
    if (ch < CCn) {
        size_t base = ((size_t)(b * 4 + t) * THW + p) * CCn + ch;
        val = 0.25f * (d_R[base] +
                       d_R[base + (size_t)1 * HW * CCn] +
                       d_R[base + (size_t)2 * HW * CCn] +
                       d_R[base + (size_t)3 * HW * CCn]);
    } else if (ch < 2 * CCn) {
        val = d_qmv[((size_t)b * 768 + 512 + (ch - CCn)) * THW + n];
    } else {
        int j = ch - 512;
        int c = j >> 2, tm = j & 3;
        size_t loc = (size_t)(b * 16 + tm * 4 + t) * HW + p;
        float raw = d_Craw[(size_t)c * NLOC + loc];
        float g, bb;
        if      (c < CPn)     { g = gc[c];           bb = bc[c]; }
        else if (c < 2 * CPn) { g = gs[c - CPn];     bb = bsv[c - CPn]; }
        else                  { g = gm[c - 2 * CPn]; bb = bmv[c - 2 * CPn]; }
        val = fmaxf((raw - d_cmean[c]) * d_crstd[c] * g + bb, 0.f);
    }
    d_Y[idx] = val;
}

__global__ void __launch_bounds__(256) k_gemm_agg(const float* __restrict__ Wagg)
{
    int b = blockIdx.z;
    gemm3t(Wagg, d_Y + (size_t)b * AGGIN * THW, d_Z + (size_t)b * Cin * THW,
           Cin, THW, AGGIN, AGGIN, THW, THW, 1.f);
}

__global__ void __launch_bounds__(256) k_finalize(const float* __restrict__ g,
                                                  const float* __restrict__ bv,
                                                  float* __restrict__ out)
{
    size_t idx = (size_t)blockIdx.x * 256 + threadIdx.x;
    if (idx >= (size_t)Bn * Cin * THW) return;
    int o = (int)((idx / THW) % Cin);
    float z = (d_Z[idx] - d_zmean[o]) * d_zrstd[o] * g[o] + bv[o];
    out[idx] = fmaxf(d_xp[idx] + z, 0.f);
}

extern "C" void kernel_launch(void* const* d_in, const int* in_sizes, int n_in,
                              void* d_out, int out_size)
{
    const float* x     = (const float*)d_in[0];
    const float* Wq    = (const float*)d_in[1];
    const float* Wm    = (const float*)d_in[2];
    const float* Wv    = (const float*)d_in[3];
    const float* Wcat  = (const float*)d_in[4];
    const float* Wsub  = (const float*)d_in[5];
    const float* Wmul  = (const float*)d_in[6];
    const float* g_cat = (const float*)d_in[7];
    const float* b_cat = (const float*)d_in[8];
    const float* g_sub = (const float*)d_in[9];
    const float* b_sub = (const float*)d_in[10];
    const float* g_mul = (const float*)d_in[11];
    const float* b_mul = (const float*)d_in[12];
    const float* Wagg  = (const float*)d_in[13];
    const float* g_agg = (const float*)d_in[14];
    const float* b_agg = (const float*)d_in[15];
    float* out = (float*)d_out;

    cudaFuncSetAttribute(k_attn, cudaFuncAttributeMaxDynamicSharedMemorySize, AT_SMEM_BYTES);

    k_pool<<<(Bn * Cin * Tn * HW + 255) / 256, 256>>>(x);
    k_gemm_qmv<<<dim3((THW + 127) / 128, CCn / 128, Bn * 3), 256>>>(Wq, Wm, Wv);
    k_qvt<<<dim3((THW + 31) / 32, CCn / 32, Bn * 3), 256>>>();
    k_attn<<<dim3(NQT, Tn, Bn), 256, AT_SMEM_BYTES>>>();
    k_wtprep<<<(256 * 168 + 255) / 256, 256>>>(Wcat, Wsub, Wmul);
    k_compare<<<NLOC / 16, 128>>>();
    k_stats_c<<<CP3, 256>>>();
    k_ybuild<<<(int)(((size_t)Bn * AGGIN * THW + 255) / 256), 256>>>(g_cat, b_cat, g_sub, b_sub, g_mul, b_mul);
    k_gemm_agg<<<dim3((THW + 127) / 128, Cin / 128, Bn), 256>>>(Wagg);
    k_stats_z<<<Cin, 256>>>();
    k_finalize<<<(Bn * Cin * THW + 255) / 256, 256>>>(g_agg, b_agg, out);
}